// round 1
// baseline (speedup 1.0000x reference)
#include <cuda_runtime.h>
#include <math.h>

#define Bb 4
#define Tt 2048
#define Cc 768
#define DKk 96
#define Nanc 8
#define NCH 32
#define LCH 64          /* Tt / NCH */
#define NSB 4
#define SBLEN 512
#define TTILE 128
#define MTOT (Bb*Tt)    /* 8192 */

/* ------------ device scratch (static, no allocation) ------------- */
__device__ float d_xproj[MTOT*Cc];
__device__ float d_ctxg [MTOT*Cc];
__device__ float d_bf   [MTOT*Cc];
__device__ float d_bs   [MTOT*Cc];
__device__ float d_cf   [MTOT*Cc];
__device__ float d_cs   [MTOT*Cc];
__device__ float d_gfr  [MTOT*Cc];
__device__ float d_gsr  [MTOT*Cc];
__device__ float d_somar[MTOT*Cc];
__device__ float d_q    [MTOT*DKk];
__device__ float d_k    [MTOT*DKk];
__device__ float d_pm   [MTOT*NSB];
__device__ float d_cg   [MTOT];
__device__ float d_xa   [Bb*Nanc*Cc];
__device__ float d_ancha[Bb*Nanc*Cc];
__device__ float d_delta[Bb*Cc];
__device__ float d_carG [Bb*NCH*Cc];
__device__ float d_carF [Bb*NCH*Cc];
__device__ float d_carS [Bb*NCH*Cc];

/* ---------------- helpers ---------------- */
__device__ __forceinline__ float alpha_of(const float* tau){
    float t = *tau;
    float sp = (t > 20.f) ? t : log1pf(expf(t));
    return expf(-sp);
}
__device__ __forceinline__ float sigmoidf_(float v){ return 1.f/(1.f+expf(-v)); }

/* ---------------- GEMM:  out = epi( A1@W1^T (+ A2@W2^T) + bias )
   A: M x K row-major, W: N x K row-major.
   epi: 0 = none, 1 = tanh, 2 = sigmoid(acc)*mult  ---------------- */
__global__ void __launch_bounds__(256)
gemm_k(const float* __restrict__ A1, const float* __restrict__ W1, int K1,
       const float* __restrict__ A2, const float* __restrict__ W2, int K2,
       const float* __restrict__ bias, const float* __restrict__ mult,
       float* __restrict__ out, int M, int N, int epi)
{
    __shared__ float As[8][128];
    __shared__ float Bs[8][128];
    int tid  = threadIdx.x;
    int row0 = blockIdx.y * 128;
    int col0 = blockIdx.x * 128;
    int tx = tid & 15, ty = tid >> 4;
    float acc[8][8];
#pragma unroll
    for (int i=0;i<8;i++)
#pragma unroll
        for (int j=0;j<8;j++) acc[i][j]=0.f;

    int lr = tid >> 1;          /* 0..127 */
    int lc = (tid & 1) * 4;     /* 0 or 4 */

    for (int seg = 0; seg < 2; seg++){
        const float* A = seg ? A2 : A1;
        const float* W = seg ? W2 : W1;
        int K = seg ? K2 : K1;
        if (A == nullptr) continue;
        for (int k0 = 0; k0 < K; k0 += 8){
            float4 av = make_float4(0,0,0,0), wv = make_float4(0,0,0,0);
            int gr = row0 + lr;
            if (gr < M) av = *(const float4*)(A + (long)gr*K + k0 + lc);
            int gc = col0 + lr;
            if (gc < N) wv = *(const float4*)(W + (long)gc*K + k0 + lc);
            As[lc+0][lr]=av.x; As[lc+1][lr]=av.y; As[lc+2][lr]=av.z; As[lc+3][lr]=av.w;
            Bs[lc+0][lr]=wv.x; Bs[lc+1][lr]=wv.y; Bs[lc+2][lr]=wv.z; Bs[lc+3][lr]=wv.w;
            __syncthreads();
#pragma unroll
            for (int kk=0; kk<8; kk++){
                float4 a0 = *(const float4*)&As[kk][ty*8];
                float4 a1 = *(const float4*)&As[kk][ty*8+4];
                float4 b0 = *(const float4*)&Bs[kk][tx*8];
                float4 b1 = *(const float4*)&Bs[kk][tx*8+4];
                float ar[8]={a0.x,a0.y,a0.z,a0.w,a1.x,a1.y,a1.z,a1.w};
                float br[8]={b0.x,b0.y,b0.z,b0.w,b1.x,b1.y,b1.z,b1.w};
#pragma unroll
                for (int i=0;i<8;i++)
#pragma unroll
                    for (int j=0;j<8;j++)
                        acc[i][j] += ar[i]*br[j];
            }
            __syncthreads();
        }
    }
#pragma unroll
    for (int i=0;i<8;i++){
        int r = row0 + ty*8 + i;
        if (r >= M) continue;
#pragma unroll
        for (int j=0;j<8;j++){
            int c = col0 + tx*8 + j;
            if (c >= N) continue;
            float v = acc[i][j];
            if (bias) v += bias[c];
            if (epi == 1)      v = tanhf(v);
            else if (epi == 2) v = mult[(long)r*N + c] * sigmoidf_(v);
            out[(long)r*N + c] = v;
        }
    }
}

/* ---------------- EMA: 3-phase chunked scan over T ---------------- */
__global__ void ema_p1(const float* __restrict__ in, float* __restrict__ outp,
                       float* __restrict__ carry, const float* __restrict__ tau)
{
    int c  = blockIdx.y*256 + threadIdx.x;
    int b  = blockIdx.x / NCH, ch = blockIdx.x % NCH;
    float alpha = alpha_of(tau);
    const float* p  = in   + ((long)b*Tt + ch*LCH)*Cc + c;
    float*       po = outp + ((long)b*Tt + ch*LCH)*Cc + c;
    float h = 0.f;
#pragma unroll 8
    for (int t=0; t<LCH; t++){
        h = alpha*h + p[(long)t*Cc];
        po[(long)t*Cc] = h;
    }
    carry[((long)b*NCH + ch)*Cc + c] = h;
}

__global__ void ema_p2(float* carry, const float* __restrict__ tau)
{
    int i = blockIdx.x*256 + threadIdx.x;
    if (i >= Bb*Cc) return;
    int b = i / Cc, c = i % Cc;
    float alpha = alpha_of(tau);
    float aL = powf(alpha, (float)LCH);
    float H = 0.f;
    for (int ch=0; ch<NCH; ch++){
        float* pc = &carry[((long)b*NCH+ch)*Cc + c];
        float cv = *pc;
        *pc = H;                 /* exclusive prefix: carry entering this chunk */
        H = aL*H + cv;
    }
}

__global__ void ema_p3(float* __restrict__ h, const float* __restrict__ carry,
                       const float* __restrict__ tau,
                       const float* __restrict__ cg, const float* __restrict__ delta)
{
    int c  = blockIdx.y*256 + threadIdx.x;
    int b  = blockIdx.x / NCH, ch = blockIdx.x % NCH;
    float alpha = alpha_of(tau);
    float P = carry[((long)b*NCH+ch)*Cc + c];
    float* p = h + ((long)b*Tt + ch*LCH)*Cc + c;
    const float* cgp = cg ? (cg + (long)b*Tt + ch*LCH) : nullptr;
    float dl = delta ? delta[(long)b*Cc + c] : 0.f;
    float ap = alpha;
#pragma unroll 8
    for (int t=0; t<LCH; t++){
        float v = p[(long)t*Cc] + ap*P;
        if (cgp) v = v*cgp[t] + dl;
        p[(long)t*Cc] = v;
        ap *= alpha;
    }
}

/* ---------------- causal max-score attention ---------------- */
__global__ void __launch_bounds__(128)
attn_partmax(const float* __restrict__ q, const float* __restrict__ kg,
             float* __restrict__ pm)
{
    const int nt = Tt / TTILE;
    int b  = blockIdx.x / nt, tt = blockIdx.x % nt;
    int sb = blockIdx.y;
    int t  = tt*TTILE + threadIdx.x;
    int tmax = tt*TTILE + TTILE - 1;
    int s_begin = sb * SBLEN;
    float m = -INFINITY;
    if (s_begin <= tmax){
        float qr[DKk];
        const float4* qp = (const float4*)(q + ((long)b*Tt + t)*DKk);
#pragma unroll
        for (int i=0;i<DKk/4;i++){
            float4 v = qp[i];
            qr[4*i]=v.x; qr[4*i+1]=v.y; qr[4*i+2]=v.z; qr[4*i+3]=v.w;
        }
        __shared__ float ksh[64*DKk];
        int s_end = min(s_begin + SBLEN, tmax + 1);
        for (int s0 = s_begin; s0 < s_end; s0 += 64){
            __syncthreads();
            const float4* kp = (const float4*)(kg + ((long)b*Tt + s0)*DKk);
            float4* kd = (float4*)ksh;
            for (int i = threadIdx.x; i < 64*DKk/4; i += 128) kd[i] = kp[i];
            __syncthreads();
            int ssmax = min(64, t - s0 + 1);
            for (int ss=0; ss<ssmax; ss++){
                const float* kr = &ksh[ss*DKk];
                float a0=0.f,a1=0.f,a2=0.f,a3=0.f;
#pragma unroll
                for (int d=0; d<DKk; d+=16){
                    float4 k0 = *(const float4*)&kr[d];
                    float4 k1 = *(const float4*)&kr[d+4];
                    float4 k2 = *(const float4*)&kr[d+8];
                    float4 k3 = *(const float4*)&kr[d+12];
                    a0 += qr[d+0]*k0.x + qr[d+1]*k0.y + qr[d+2]*k0.z + qr[d+3]*k0.w;
                    a1 += qr[d+4]*k1.x + qr[d+5]*k1.y + qr[d+6]*k1.z + qr[d+7]*k1.w;
                    a2 += qr[d+8]*k2.x + qr[d+9]*k2.y + qr[d+10]*k2.z + qr[d+11]*k2.w;
                    a3 += qr[d+12]*k3.x + qr[d+13]*k3.y + qr[d+14]*k3.z + qr[d+15]*k3.w;
                }
                m = fmaxf(m, (a0+a1)+(a2+a3));
            }
        }
    }
    pm[((long)b*Tt + t)*NSB + sb] = m;
}

__global__ void attn_reduce(const float* __restrict__ pm, float* __restrict__ cgout)
{
    int i = blockIdx.x*256 + threadIdx.x;
    if (i >= MTOT) return;
    float m = pm[(long)i*NSB];
#pragma unroll
    for (int j=1;j<NSB;j++) m = fmaxf(m, pm[(long)i*NSB + j]);
    m *= rsqrtf((float)DKk);
    cgout[i] = sigmoidf_(m);
}

/* ---------------- anchors ---------------- */
__global__ void anchor_gather(const float* __restrict__ x, float* __restrict__ xa)
{
    int i = blockIdx.x*256 + threadIdx.x;
    if (i >= Bb*Nanc*Cc) return;
    int c = i % Cc;
    int n = (i / Cc) % Nanc;
    int b = i / (Cc*Nanc);
    int pos = n * (Tt / Nanc);
    if (pos > Tt-1) pos = Tt-1;
    xa[i] = x[((long)b*Tt + pos)*Cc + c];
}

__global__ void delta_k(const float* __restrict__ ancha, const float* __restrict__ scales,
                        float* __restrict__ delta)
{
    int i = blockIdx.x*256 + threadIdx.x;
    if (i >= Bb*Cc) return;
    int b = i / Cc, c = i % Cc;
    float s = 0.f;
#pragma unroll
    for (int n=0;n<Nanc;n++){
        float sg = sigmoidf_(scales[n]);
        s += sg * ancha[((long)b*Nanc + n)*Cc + c];
    }
    delta[i] = s;
}

/* ---------------- final gate + layernorm ---------------- */
__global__ void __launch_bounds__(256)
final_k(const float* __restrict__ gfr, const float* __restrict__ gsr,
        const float* __restrict__ somar, const float* __restrict__ blend,
        const float* __restrict__ lng, const float* __restrict__ lnb,
        float* __restrict__ out)
{
    long row = blockIdx.x;
    int tid = threadIdx.x;
    float bl = sigmoidf_(blend[0]);
    float y[3]; float s = 0.f, sq = 0.f;
#pragma unroll
    for (int j=0;j<3;j++){
        int c = tid + j*256;
        long idx = row*Cc + c;
        float f  = sigmoidf_(gfr[idx]);
        float g2 = sigmoidf_(gsr[idx]);
        float gate = f + bl*(g2 - f);
        float v = tanhf(somar[idx]) * gate;
        y[j] = v; s += v; sq += v*v;
    }
    __shared__ float rs[8], rq[8];
#pragma unroll
    for (int o=16;o>0;o>>=1){
        s  += __shfl_xor_sync(0xffffffffu, s,  o);
        sq += __shfl_xor_sync(0xffffffffu, sq, o);
    }
    if ((tid & 31) == 0){ rs[tid>>5] = s; rq[tid>>5] = sq; }
    __syncthreads();
    if (tid == 0){
        float ts=0.f, tq=0.f;
#pragma unroll
        for (int w=0;w<8;w++){ ts += rs[w]; tq += rq[w]; }
        rs[0] = ts; rq[0] = tq;
    }
    __syncthreads();
    float mu  = rs[0] / Cc;
    float var = rq[0] / Cc - mu*mu;
    float inv = rsqrtf(var + 1e-5f);
#pragma unroll
    for (int j=0;j<3;j++){
        int c = tid + j*256;
        long idx = row*Cc + c;
        out[idx] = (y[j]-mu)*inv*lng[c] + lnb[c];
    }
}

/* ---------------- launch ---------------- */
static float* symaddr(const void* sym){
    void* p = nullptr;
    cudaGetSymbolAddress(&p, sym);
    return (float*)p;
}

extern "C" void kernel_launch(void* const* d_in, const int* in_sizes, int n_in,
                              void* d_out, int out_size)
{
    const float* x        = (const float*)d_in[0];
    const float* tau_gate = (const float*)d_in[1];
    const float* tau_fast = (const float*)d_in[2];
    const float* tau_slow = (const float*)d_in[3];
    const float* Wp   = (const float*)d_in[4];
    const float* bp   = (const float*)d_in[5];
    const float* Wxf  = (const float*)d_in[6];
    const float* bxf  = (const float*)d_in[7];
    const float* Wxs  = (const float*)d_in[8];
    const float* bxs  = (const float*)d_in[9];
    const float* Wcf  = (const float*)d_in[10];
    const float* Wcs  = (const float*)d_in[11];
    const float* Wq   = (const float*)d_in[12];
    const float* Wk   = (const float*)d_in[13];
    const float* Wfast= (const float*)d_in[14];
    const float* bfast= (const float*)d_in[15];
    const float* Wslow= (const float*)d_in[16];
    const float* bslow= (const float*)d_in[17];
    const float* Wsoma= (const float*)d_in[18];
    const float* bsoma= (const float*)d_in[19];
    const float* Wanc = (const float*)d_in[20];
    const float* banc = (const float*)d_in[21];
    const float* ascl = (const float*)d_in[22];
    const float* blend= (const float*)d_in[23];
    const float* lng  = (const float*)d_in[24];
    const float* lnb  = (const float*)d_in[25];
    float* out = (float*)d_out;

    float* xproj = symaddr(d_xproj);
    float* ctxg  = symaddr(d_ctxg);
    float* bfp   = symaddr(d_bf);
    float* bsp   = symaddr(d_bs);
    float* cfp   = symaddr(d_cf);
    float* csp   = symaddr(d_cs);
    float* gfr   = symaddr(d_gfr);
    float* gsr   = symaddr(d_gsr);
    float* somar = symaddr(d_somar);
    float* qp    = symaddr(d_q);
    float* kp    = symaddr(d_k);
    float* pm    = symaddr(d_pm);
    float* cg    = symaddr(d_cg);
    float* xa    = symaddr(d_xa);
    float* ancha = symaddr(d_ancha);
    float* delta = symaddr(d_delta);
    float* carG  = symaddr(d_carG);
    float* carF  = symaddr(d_carF);
    float* carS  = symaddr(d_carS);

    dim3 blk(256);
    dim3 gbig(Cc/128, MTOT/128);          /* 6 x 64 */
    dim3 gqk(1, MTOT/128);                /* N=96 */
    dim3 ganc(Cc/128, 1);                 /* M=32  */
    dim3 gema(Bb*NCH, Cc/256);            /* 128 x 3 */

    /* x_proj = tanh(x@Wp^T + bp) */
    gemm_k<<<gbig, blk>>>(x, Wp, Cc, nullptr, nullptr, 0, bp, nullptr, xproj, MTOT, Cc, 1);

    /* q, k */
    gemm_k<<<gqk, blk>>>(x, Wq, Cc, nullptr, nullptr, 0, nullptr, nullptr, qp, MTOT, DKk, 0);
    gemm_k<<<gqk, blk>>>(x, Wk, Cc, nullptr, nullptr, 0, nullptr, nullptr, kp, MTOT, DKk, 0);

    /* content gate cg */
    dim3 ga(Bb*(Tt/TTILE), NSB);
    attn_partmax<<<ga, 128>>>(qp, kp, pm);
    attn_reduce<<<(MTOT+255)/256, 256>>>(pm, cg);

    /* anchors -> delta */
    anchor_gather<<<(Bb*Nanc*Cc+255)/256, 256>>>(x, xa);
    gemm_k<<<ganc, blk>>>(xa, Wanc, Cc, nullptr, nullptr, 0, banc, nullptr, ancha, Bb*Nanc, Cc, 1);
    delta_k<<<(Bb*Cc+255)/256, 256>>>(ancha, ascl, delta);

    /* ctx_gate EMA */
    ema_p1<<<gema, 256>>>(x, ctxg, carG, tau_gate);
    ema_p2<<<(Bb*Cc+255)/256, 256>>>(carG, tau_gate);
    ema_p3<<<gema, 256>>>(ctxg, carG, tau_gate, nullptr, nullptr);

    /* bf = x_proj * sigmoid(x@Wxf^T + ctxg@Wcf^T + bxf); same for slow */
    gemm_k<<<gbig, blk>>>(x, Wxf, Cc, ctxg, Wcf, Cc, bxf, xproj, bfp, MTOT, Cc, 2);
    gemm_k<<<gbig, blk>>>(x, Wxs, Cc, ctxg, Wcs, Cc, bxs, xproj, bsp, MTOT, Cc, 2);

    /* ctx_fast / ctx_slow EMAs, with *cg + delta fused into phase 3 */
    ema_p1<<<gema, 256>>>(bfp, cfp, carF, tau_fast);
    ema_p1<<<gema, 256>>>(bsp, csp, carS, tau_slow);
    ema_p2<<<(Bb*Cc+255)/256, 256>>>(carF, tau_fast);
    ema_p2<<<(Bb*Cc+255)/256, 256>>>(carS, tau_slow);
    ema_p3<<<gema, 256>>>(cfp, carF, tau_fast, cg, delta);
    ema_p3<<<gema, 256>>>(csp, carS, tau_slow, cg, delta);

    /* gate pre-activations + soma pre-activation */
    gemm_k<<<gbig, blk>>>(cfp, Wfast, Cc, nullptr, nullptr, 0, bfast, nullptr, gfr,  MTOT, Cc, 0);
    gemm_k<<<gbig, blk>>>(csp, Wslow, Cc, nullptr, nullptr, 0, bslow, nullptr, gsr,  MTOT, Cc, 0);
    gemm_k<<<gbig, blk>>>(x,   Wsoma, Cc, nullptr, nullptr, 0, bsoma, nullptr, somar,MTOT, Cc, 0);

    /* fused gates + layernorm */
    final_k<<<MTOT, 256>>>(gfr, gsr, somar, blend, lng, lnb, out);
}

// round 3
// speedup vs baseline: 2.5646x; 2.5646x over previous
#include <cuda_runtime.h>
#include <cuda_bf16.h>
#include <cstdint>
#include <math.h>

#define Bb 4
#define Tt 2048
#define Cc 768
#define DKk 96
#define Nanc 8
#define NCH 32
#define LCH 64          /* Tt / NCH */
#define NSB 8
#define SBLEN 256
#define TTILE 128
#define MTOT (Bb*Tt)    /* 8192 */

#define KSPLIT 2304     /* 3 * 768 split-bf16 expanded K */
#define BKs 32          /* K per stage */
#define STA 40          /* smem row stride in bf16 (80 bytes) */
#define TILE_BYTES (128*STA*2)          /* 10240 */
#define STG_BYTES (2*TILE_BYTES)        /* A+B per stage: 20480 */
#define NSTG 4
#define SMEMSZ (NSTG*STG_BYTES + 256)

/* ------------ device scratch (static, no allocation) ------------- */
__device__ float d_xproj[MTOT*Cc];
__device__ float d_ctxg [MTOT*Cc];
__device__ float d_bf   [MTOT*Cc];
__device__ float d_bs   [MTOT*Cc];
__device__ float d_cf   [MTOT*Cc];
__device__ float d_cs   [MTOT*Cc];
__device__ float d_gfr  [MTOT*Cc];
__device__ float d_gsr  [MTOT*Cc];
__device__ float d_somar[MTOT*Cc];
__device__ float d_q    [MTOT*DKk];
__device__ float d_k    [MTOT*DKk];
__device__ float d_pm   [MTOT*NSB];
__device__ float d_cg   [MTOT];
__device__ float d_xa   [Bb*Nanc*Cc];
__device__ float d_ancha[Bb*Nanc*Cc];
__device__ float d_delta[Bb*Cc];
__device__ float d_carG [Bb*NCH*Cc];
__device__ float d_carF [Bb*NCH*Cc];
__device__ float d_carS [Bb*NCH*Cc];

/* split-bf16 expanded buffers */
__device__ __nv_bfloat16 d_xS   [(long)MTOT*KSPLIT];
__device__ __nv_bfloat16 d_ctxgS[(long)MTOT*KSPLIT];
__device__ __nv_bfloat16 d_cfS  [(long)MTOT*KSPLIT];
__device__ __nv_bfloat16 d_csS  [(long)MTOT*KSPLIT];
__device__ __nv_bfloat16 d_WpS   [768*KSPLIT];
__device__ __nv_bfloat16 d_WxfS  [768*KSPLIT];
__device__ __nv_bfloat16 d_WxsS  [768*KSPLIT];
__device__ __nv_bfloat16 d_WcfS  [768*KSPLIT];
__device__ __nv_bfloat16 d_WcsS  [768*KSPLIT];
__device__ __nv_bfloat16 d_WfastS[768*KSPLIT];
__device__ __nv_bfloat16 d_WslowS[768*KSPLIT];
__device__ __nv_bfloat16 d_WsomaS[768*KSPLIT];
__device__ __nv_bfloat16 d_WqS   [128*KSPLIT];
__device__ __nv_bfloat16 d_WkS   [128*KSPLIT];

/* ---------------- helpers ---------------- */
__device__ __forceinline__ float alpha_of(const float* tau){
    float t = *tau;
    float sp = (t > 20.f) ? t : log1pf(expf(t));
    return expf(-sp);
}
__device__ __forceinline__ float sigmoidf_(float v){ return 1.f/(1.f+expf(-v)); }

__device__ __forceinline__ uint32_t smem_u32(const void* p){
    uint32_t a;
    asm("{ .reg .u64 t; cvta.to.shared.u64 t, %1; cvt.u32.u64 %0, t; }" : "=r"(a) : "l"(p));
    return a;
}

__device__ __forceinline__ void cp_async16(uint32_t dst, const void* src){
    asm volatile("cp.async.cg.shared.global [%0], [%1], 16;" :: "r"(dst), "l"(src));
}
__device__ __forceinline__ void cp_commit(){ asm volatile("cp.async.commit_group;" ::: "memory"); }
template<int N> __device__ __forceinline__ void cp_wait(){ asm volatile("cp.async.wait_group %0;" :: "n"(N) : "memory"); }

__device__ __forceinline__ void ldm_x4(uint32_t addr, uint32_t& r0, uint32_t& r1, uint32_t& r2, uint32_t& r3){
    asm volatile("ldmatrix.sync.aligned.m8n8.x4.shared.b16 {%0,%1,%2,%3}, [%4];"
        : "=r"(r0), "=r"(r1), "=r"(r2), "=r"(r3) : "r"(addr));
}
__device__ __forceinline__ void mma16816(float& c0, float& c1, float& c2, float& c3,
                                         uint32_t a0, uint32_t a1, uint32_t a2, uint32_t a3,
                                         uint32_t b0, uint32_t b1){
    asm volatile("mma.sync.aligned.m16n8k16.row.col.f32.bf16.bf16.f32 "
        "{%0,%1,%2,%3}, {%4,%5,%6,%7}, {%8,%9}, {%0,%1,%2,%3};"
        : "+f"(c0), "+f"(c1), "+f"(c2), "+f"(c3)
        : "r"(a0), "r"(a1), "r"(a2), "r"(a3), "r"(b0), "r"(b1));
}

/* ---------------- split-bf16 conversion kernels ---------------- */
__global__ void split_act(const float* __restrict__ in, __nv_bfloat16* __restrict__ out)
{
    long i = (long)blockIdx.x*256 + threadIdx.x;  /* over MTOT*192 float4 groups */
    if (i >= (long)MTOT*192) return;
    long r = i / 192; int c4 = (int)(i % 192);
    float4 v = *(const float4*)(in + r*768 + c4*4);
    __nv_bfloat16 h0=__float2bfloat16(v.x), h1=__float2bfloat16(v.y),
                  h2=__float2bfloat16(v.z), h3=__float2bfloat16(v.w);
    __nv_bfloat16 l0=__float2bfloat16(v.x-__bfloat162float(h0));
    __nv_bfloat16 l1=__float2bfloat16(v.y-__bfloat162float(h1));
    __nv_bfloat16 l2=__float2bfloat16(v.z-__bfloat162float(h2));
    __nv_bfloat16 l3=__float2bfloat16(v.w-__bfloat162float(h3));
    __nv_bfloat162 hA; hA.x=h0; hA.y=h1;
    __nv_bfloat162 hB; hB.x=h2; hB.y=h3;
    __nv_bfloat162 lA; lA.x=l0; lA.y=l1;
    __nv_bfloat162 lB; lB.x=l2; lB.y=l3;
    __nv_bfloat162* o0 = (__nv_bfloat162*)(out + r*KSPLIT + c4*4);
    __nv_bfloat162* o1 = (__nv_bfloat162*)(out + r*KSPLIT + 768 + c4*4);
    __nv_bfloat162* o2 = (__nv_bfloat162*)(out + r*KSPLIT + 1536 + c4*4);
    o0[0]=hA; o0[1]=hB;         /* hi */
    o1[0]=hA; o1[1]=hB;         /* hi */
    o2[0]=lA; o2[1]=lB;         /* lo */
}

__global__ void split_w(const float* __restrict__ W, __nv_bfloat16* __restrict__ out,
                        int Nsrc, int Npad)
{
    long i = (long)blockIdx.x*256 + threadIdx.x;
    if (i >= (long)Npad*192) return;
    int r = (int)(i / 192); int c4 = (int)(i % 192);
    float4 v = make_float4(0.f,0.f,0.f,0.f);
    if (r < Nsrc) v = *(const float4*)(W + (long)r*768 + c4*4);
    __nv_bfloat16 h0=__float2bfloat16(v.x), h1=__float2bfloat16(v.y),
                  h2=__float2bfloat16(v.z), h3=__float2bfloat16(v.w);
    __nv_bfloat16 l0=__float2bfloat16(v.x-__bfloat162float(h0));
    __nv_bfloat16 l1=__float2bfloat16(v.y-__bfloat162float(h1));
    __nv_bfloat16 l2=__float2bfloat16(v.z-__bfloat162float(h2));
    __nv_bfloat16 l3=__float2bfloat16(v.w-__bfloat162float(h3));
    __nv_bfloat162 hA; hA.x=h0; hA.y=h1;
    __nv_bfloat162 hB; hB.x=h2; hB.y=h3;
    __nv_bfloat162 lA; lA.x=l0; lA.y=l1;
    __nv_bfloat162 lB; lB.x=l2; lB.y=l3;
    __nv_bfloat162* o0 = (__nv_bfloat162*)(out + (long)r*KSPLIT + c4*4);
    __nv_bfloat162* o1 = (__nv_bfloat162*)(out + (long)r*KSPLIT + 768 + c4*4);
    __nv_bfloat162* o2 = (__nv_bfloat162*)(out + (long)r*KSPLIT + 1536 + c4*4);
    o0[0]=hA; o0[1]=hB;         /* hi */
    o1[0]=lA; o1[1]=lB;         /* lo */
    o2[0]=hA; o2[1]=hB;         /* hi */
}

/* ---------------- mma.sync GEMM ----------------
   out[M, Nout] = epi( sum_seg A_seg[M,2304] @ B_seg[Npad,2304]^T + bias )
   CTA tile 128x128, BK=32, 8 warps (4m x 2n), warp tile 32x64.
   epi: 0 none, 1 tanh, 2 sigmoid(acc)*mult                              */
__device__ __forceinline__ void load_stage(const __nv_bfloat16* __restrict__ A,
                                           const __nv_bfloat16* __restrict__ Bp,
                                           int kofs, uint32_t sbuf, int tid)
{
    uint32_t sA = sbuf, sB = sbuf + TILE_BYTES;
#pragma unroll
    for (int it = 0; it < 2; it++){        /* A: 128 rows x 4 chunks of 16B */
        int ci = it*256 + tid;
        int row = ci >> 2, c = ci & 3;
        cp_async16(sA + row*80 + c*16, A + (long)row*KSPLIT + kofs + c*8);
    }
#pragma unroll
    for (int it = 0; it < 2; it++){        /* B: 128 rows x 4 chunks */
        int ci = it*256 + tid;
        int row = ci >> 2, c = ci & 3;
        cp_async16(sB + row*80 + c*16, Bp + (long)row*KSPLIT + kofs + c*8);
    }
    cp_commit();
}

__global__ void __launch_bounds__(256)
mma_gemm(const __nv_bfloat16* __restrict__ A1, const __nv_bfloat16* __restrict__ B1,
         const __nv_bfloat16* __restrict__ A2, const __nv_bfloat16* __restrict__ B2,
         int nseg, const float* __restrict__ bias, const float* __restrict__ mult,
         float* __restrict__ out, int Nout, int epi)
{
    extern __shared__ char dyn[];
    const int tid  = threadIdx.x;
    const int lane = tid & 31;
    const int wid  = tid >> 5;
    const int wm   = wid & 3;        /* 0..3 : m */
    const int wn   = wid >> 2;       /* 0..1 : n */
    const int row0 = blockIdx.y * 128;
    const int col0 = blockIdx.x * 128;
    uint32_t sbase = (smem_u32(dyn) + 127u) & ~127u;

    const __nv_bfloat16* Aseg[2];
    const __nv_bfloat16* Bseg[2];
    Aseg[0] = A1 + (long)row0*KSPLIT;
    Bseg[0] = B1 + (long)col0*KSPLIT;
    Aseg[1] = A2 ? (A2 + (long)row0*KSPLIT) : Aseg[0];
    Bseg[1] = B2 ? (B2 + (long)col0*KSPLIT) : Bseg[0];
    const int SPS = KSPLIT / BKs;            /* 72 stages per segment */
    const int S = SPS * nseg;

    float acc[2][8][4];
#pragma unroll
    for (int i=0;i<2;i++)
#pragma unroll
        for (int j=0;j<8;j++)
#pragma unroll
            for (int r=0;r<4;r++) acc[i][j][r]=0.f;

    /* ldmatrix per-thread source offsets (within tile, bytes) */
    /* A x4: t0-7: m(t&15) k0 | t8-15: m(t&15) k0 | t16-31: same rows k0+8 */
    int aM = lane & 15;
    int aK = (lane >> 4) * 8;
    /* B x4 (two n-frags per call): t0-7: n(t&7),k0 | t8-15: n(t&7),k8 | t16-23: n8+(t&7),k0 | t24-31: n8+(t&7),k8 */
    int bN = ((lane >> 4) & 1)*8 + (lane & 7);
    int bK = ((lane >> 3) & 1)*8;

    /* prologue: stages 0..NSTG-2 */
#pragma unroll
    for (int p = 0; p < NSTG-1; p++)
        load_stage(Aseg[0], Bseg[0], p*BKs, sbase + p*STG_BYTES, tid);

    for (int s = 0; s < S; s++){
        cp_wait<NSTG-2>();
        __syncthreads();
        uint32_t sA = sbase + (s % NSTG)*STG_BYTES;
        uint32_t sB = sA + TILE_BYTES;
#pragma unroll
        for (int ks = 0; ks < 2; ks++){
            int k0 = ks*16;
            uint32_t a[2][4];
#pragma unroll
            for (int i=0;i<2;i++){
                uint32_t ad = sA + (uint32_t)(wm*32 + i*16 + aM)*80 + (uint32_t)(k0 + aK)*2;
                ldm_x4(ad, a[i][0], a[i][1], a[i][2], a[i][3]);
            }
            uint32_t b[8][2];
#pragma unroll
            for (int jj=0;jj<4;jj++){
                uint32_t bd = sB + (uint32_t)(wn*64 + jj*16 + bN)*80 + (uint32_t)(k0 + bK)*2;
                uint32_t r0,r1,r2,r3;
                ldm_x4(bd, r0, r1, r2, r3);
                b[2*jj][0]=r0; b[2*jj][1]=r1; b[2*jj+1][0]=r2; b[2*jj+1][1]=r3;
            }
#pragma unroll
            for (int i=0;i<2;i++)
#pragma unroll
                for (int j=0;j<8;j++)
                    mma16816(acc[i][j][0], acc[i][j][1], acc[i][j][2], acc[i][j][3],
                             a[i][0], a[i][1], a[i][2], a[i][3], b[j][0], b[j][1]);
        }
        int nl = s + NSTG - 1;
        if (nl < S){
            int seg = (nl >= SPS) ? 1 : 0;
            int ko  = (nl - seg*SPS) * BKs;
            load_stage(Aseg[seg], Bseg[seg], ko, sbase + (nl % NSTG)*STG_BYTES, tid);
        }
    }

    /* epilogue */
#pragma unroll
    for (int i=0;i<2;i++){
        int rlo = row0 + wm*32 + i*16 + (lane >> 2);
#pragma unroll
        for (int j=0;j<8;j++){
            int c = col0 + wn*64 + j*8 + (lane & 3)*2;
            if (c >= Nout) continue;
#pragma unroll
            for (int h=0;h<2;h++){
                long r = rlo + h*8;
                float v0 = acc[i][j][2*h], v1 = acc[i][j][2*h+1];
                if (bias){ v0 += bias[c]; v1 += bias[c+1]; }
                if (epi == 1){ v0 = tanhf(v0); v1 = tanhf(v1); }
                else if (epi == 2){
                    float m0 = mult[r*768 + c], m1 = mult[r*768 + c + 1];
                    v0 = m0 * sigmoidf_(v0); v1 = m1 * sigmoidf_(v1);
                }
                float2 st; st.x = v0; st.y = v1;
                *(float2*)(out + r*(long)Nout + c) = st;
            }
        }
    }
}

/* ---------------- SIMT GEMM (kept for tiny anchor matmul) ---------------- */
__global__ void __launch_bounds__(256)
gemm_k(const float* __restrict__ A1, const float* __restrict__ W1, int K1,
       const float* __restrict__ bias,
       float* __restrict__ out, int M, int N, int epi)
{
    __shared__ float As[8][128];
    __shared__ float Bs[8][128];
    int tid  = threadIdx.x;
    int row0 = blockIdx.y * 128;
    int col0 = blockIdx.x * 128;
    int tx = tid & 15, ty = tid >> 4;
    float acc[8][8];
#pragma unroll
    for (int i=0;i<8;i++)
#pragma unroll
        for (int j=0;j<8;j++) acc[i][j]=0.f;

    int lr = tid >> 1;
    int lc = (tid & 1) * 4;

    for (int k0 = 0; k0 < K1; k0 += 8){
        float4 av = make_float4(0,0,0,0), wv = make_float4(0,0,0,0);
        int gr = row0 + lr;
        if (gr < M) av = *(const float4*)(A1 + (long)gr*K1 + k0 + lc);
        int gc = col0 + lr;
        if (gc < N) wv = *(const float4*)(W1 + (long)gc*K1 + k0 + lc);
        As[lc+0][lr]=av.x; As[lc+1][lr]=av.y; As[lc+2][lr]=av.z; As[lc+3][lr]=av.w;
        Bs[lc+0][lr]=wv.x; Bs[lc+1][lr]=wv.y; Bs[lc+2][lr]=wv.z; Bs[lc+3][lr]=wv.w;
        __syncthreads();
#pragma unroll
        for (int kk=0; kk<8; kk++){
            float4 a0 = *(const float4*)&As[kk][ty*8];
            float4 a1 = *(const float4*)&As[kk][ty*8+4];
            float4 b0 = *(const float4*)&Bs[kk][tx*8];
            float4 b1 = *(const float4*)&Bs[kk][tx*8+4];
            float ar[8]={a0.x,a0.y,a0.z,a0.w,a1.x,a1.y,a1.z,a1.w};
            float br[8]={b0.x,b0.y,b0.z,b0.w,b1.x,b1.y,b1.z,b1.w};
#pragma unroll
            for (int i=0;i<8;i++)
#pragma unroll
                for (int j=0;j<8;j++)
                    acc[i][j] += ar[i]*br[j];
        }
        __syncthreads();
    }
#pragma unroll
    for (int i=0;i<8;i++){
        int r = row0 + ty*8 + i;
        if (r >= M) continue;
#pragma unroll
        for (int j=0;j<8;j++){
            int c = col0 + tx*8 + j;
            if (c >= N) continue;
            float v = acc[i][j];
            if (bias) v += bias[c];
            if (epi == 1) v = tanhf(v);
            out[(long)r*N + c] = v;
        }
    }
}

/* ---------------- EMA: 3-phase chunked scan over T ---------------- */
__global__ void ema_p1(const float* __restrict__ in, float* __restrict__ outp,
                       float* __restrict__ carry, const float* __restrict__ tau)
{
    int c  = blockIdx.y*256 + threadIdx.x;
    int b  = blockIdx.x / NCH, ch = blockIdx.x % NCH;
    float alpha = alpha_of(tau);
    const float* p  = in   + ((long)b*Tt + ch*LCH)*Cc + c;
    float*       po = outp + ((long)b*Tt + ch*LCH)*Cc + c;
    float h = 0.f;
#pragma unroll 8
    for (int t=0; t<LCH; t++){
        h = alpha*h + p[(long)t*Cc];
        po[(long)t*Cc] = h;
    }
    carry[((long)b*NCH + ch)*Cc + c] = h;
}

__global__ void ema_p2(float* carry, const float* __restrict__ tau)
{
    int i = blockIdx.x*256 + threadIdx.x;
    if (i >= Bb*Cc) return;
    int b = i / Cc, c = i % Cc;
    float alpha = alpha_of(tau);
    float aL = powf(alpha, (float)LCH);
    float H = 0.f;
    for (int ch=0; ch<NCH; ch++){
        float* pc = &carry[((long)b*NCH+ch)*Cc + c];
        float cv = *pc;
        *pc = H;
        H = aL*H + cv;
    }
}

__global__ void ema_p3(float* __restrict__ h, const float* __restrict__ carry,
                       const float* __restrict__ tau,
                       const float* __restrict__ cg, const float* __restrict__ delta)
{
    int c  = blockIdx.y*256 + threadIdx.x;
    int b  = blockIdx.x / NCH, ch = blockIdx.x % NCH;
    float alpha = alpha_of(tau);
    float P = carry[((long)b*NCH+ch)*Cc + c];
    float* p = h + ((long)b*Tt + ch*LCH)*Cc + c;
    const float* cgp = cg ? (cg + (long)b*Tt + ch*LCH) : nullptr;
    float dl = delta ? delta[(long)b*Cc + c] : 0.f;
    float ap = alpha;
#pragma unroll 8
    for (int t=0; t<LCH; t++){
        float v = p[(long)t*Cc] + ap*P;
        if (cgp) v = v*cgp[t] + dl;
        p[(long)t*Cc] = v;
        ap *= alpha;
    }
}

/* ---------------- causal max-score attention ---------------- */
__global__ void __launch_bounds__(128)
attn_partmax(const float* __restrict__ q, const float* __restrict__ kg,
             float* __restrict__ pm)
{
    const int nt = Tt / TTILE;
    int b  = blockIdx.x / nt, tt = blockIdx.x % nt;
    int sb = blockIdx.y;
    int t  = tt*TTILE + threadIdx.x;
    int tmax = tt*TTILE + TTILE - 1;
    int s_begin = sb * SBLEN;
    float m = -INFINITY;
    if (s_begin <= tmax){
        float qr[DKk];
        const float4* qp = (const float4*)(q + ((long)b*Tt + t)*DKk);
#pragma unroll
        for (int i=0;i<DKk/4;i++){
            float4 v = qp[i];
            qr[4*i]=v.x; qr[4*i+1]=v.y; qr[4*i+2]=v.z; qr[4*i+3]=v.w;
        }
        __shared__ float ksh[64*DKk];
        int s_end = min(s_begin + SBLEN, tmax + 1);
        for (int s0 = s_begin; s0 < s_end; s0 += 64){
            __syncthreads();
            const float4* kp = (const float4*)(kg + ((long)b*Tt + s0)*DKk);
            float4* kd = (float4*)ksh;
            for (int i = threadIdx.x; i < 64*DKk/4; i += 128) kd[i] = kp[i];
            __syncthreads();
            int ssmax = min(64, t - s0 + 1);
            for (int ss=0; ss<ssmax; ss++){
                const float* kr = &ksh[ss*DKk];
                float a0=0.f,a1=0.f,a2=0.f,a3=0.f;
#pragma unroll
                for (int d=0; d<DKk; d+=16){
                    float4 k0 = *(const float4*)&kr[d];
                    float4 k1 = *(const float4*)&kr[d+4];
                    float4 k2 = *(const float4*)&kr[d+8];
                    float4 k3 = *(const float4*)&kr[d+12];
                    a0 += qr[d+0]*k0.x + qr[d+1]*k0.y + qr[d+2]*k0.z + qr[d+3]*k0.w;
                    a1 += qr[d+4]*k1.x + qr[d+5]*k1.y + qr[d+6]*k1.z + qr[d+7]*k1.w;
                    a2 += qr[d+8]*k2.x + qr[d+9]*k2.y + qr[d+10]*k2.z + qr[d+11]*k2.w;
                    a3 += qr[d+12]*k3.x + qr[d+13]*k3.y + qr[d+14]*k3.z + qr[d+15]*k3.w;
                }
                m = fmaxf(m, (a0+a1)+(a2+a3));
            }
        }
    }
    pm[((long)b*Tt + t)*NSB + sb] = m;
}

__global__ void attn_reduce(const float* __restrict__ pm, float* __restrict__ cgout)
{
    int i = blockIdx.x*256 + threadIdx.x;
    if (i >= MTOT) return;
    float m = pm[(long)i*NSB];
#pragma unroll
    for (int j=1;j<NSB;j++) m = fmaxf(m, pm[(long)i*NSB + j]);
    m *= rsqrtf((float)DKk);
    cgout[i] = sigmoidf_(m);
}

/* ---------------- anchors ---------------- */
__global__ void anchor_gather(const float* __restrict__ x, float* __restrict__ xa)
{
    int i = blockIdx.x*256 + threadIdx.x;
    if (i >= Bb*Nanc*Cc) return;
    int c = i % Cc;
    int n = (i / Cc) % Nanc;
    int b = i / (Cc*Nanc);
    int pos = n * (Tt / Nanc);
    if (pos > Tt-1) pos = Tt-1;
    xa[i] = x[((long)b*Tt + pos)*Cc + c];
}

__global__ void delta_k(const float* __restrict__ ancha, const float* __restrict__ scales,
                        float* __restrict__ delta)
{
    int i = blockIdx.x*256 + threadIdx.x;
    if (i >= Bb*Cc) return;
    int b = i / Cc, c = i % Cc;
    float s = 0.f;
#pragma unroll
    for (int n=0;n<Nanc;n++){
        float sg = sigmoidf_(scales[n]);
        s += sg * ancha[((long)b*Nanc + n)*Cc + c];
    }
    delta[i] = s;
}

/* ---------------- final gate + layernorm ---------------- */
__global__ void __launch_bounds__(256)
final_k(const float* __restrict__ gfr, const float* __restrict__ gsr,
        const float* __restrict__ somar, const float* __restrict__ blend,
        const float* __restrict__ lng, const float* __restrict__ lnb,
        float* __restrict__ out)
{
    long row = blockIdx.x;
    int tid = threadIdx.x;
    float bl = sigmoidf_(blend[0]);
    float y[3]; float s = 0.f, sq = 0.f;
#pragma unroll
    for (int j=0;j<3;j++){
        int c = tid + j*256;
        long idx = row*Cc + c;
        float f  = sigmoidf_(gfr[idx]);
        float g2 = sigmoidf_(gsr[idx]);
        float gate = f + bl*(g2 - f);
        float v = tanhf(somar[idx]) * gate;
        y[j] = v; s += v; sq += v*v;
    }
    __shared__ float rs[8], rq[8];
#pragma unroll
    for (int o=16;o>0;o>>=1){
        s  += __shfl_xor_sync(0xffffffffu, s,  o);
        sq += __shfl_xor_sync(0xffffffffu, sq, o);
    }
    if ((tid & 31) == 0){ rs[tid>>5] = s; rq[tid>>5] = sq; }
    __syncthreads();
    if (tid == 0){
        float ts=0.f, tq=0.f;
#pragma unroll
        for (int w=0;w<8;w++){ ts += rs[w]; tq += rq[w]; }
        rs[0] = ts; rq[0] = tq;
    }
    __syncthreads();
    float mu  = rs[0] / Cc;
    float var = rq[0] / Cc - mu*mu;
    float inv = rsqrtf(var + 1e-5f);
#pragma unroll
    for (int j=0;j<3;j++){
        int c = tid + j*256;
        long idx = row*Cc + c;
        out[idx] = (y[j]-mu)*inv*lng[c] + lnb[c];
    }
}

/* ---------------- launch ---------------- */
static float* symaddr(const void* sym){
    void* p = nullptr;
    cudaGetSymbolAddress(&p, sym);
    return (float*)p;
}
static __nv_bfloat16* symaddrb(const void* sym){
    void* p = nullptr;
    cudaGetSymbolAddress(&p, sym);
    return (__nv_bfloat16*)p;
}

extern "C" void kernel_launch(void* const* d_in, const int* in_sizes, int n_in,
                              void* d_out, int out_size)
{
    const float* x        = (const float*)d_in[0];
    const float* tau_gate = (const float*)d_in[1];
    const float* tau_fast = (const float*)d_in[2];
    const float* tau_slow = (const float*)d_in[3];
    const float* Wp   = (const float*)d_in[4];
    const float* bp   = (const float*)d_in[5];
    const float* Wxf  = (const float*)d_in[6];
    const float* bxf  = (const float*)d_in[7];
    const float* Wxs  = (const float*)d_in[8];
    const float* bxs  = (const float*)d_in[9];
    const float* Wcf  = (const float*)d_in[10];
    const float* Wcs  = (const float*)d_in[11];
    const float* Wq   = (const float*)d_in[12];
    const float* Wk   = (const float*)d_in[13];
    const float* Wfast= (const float*)d_in[14];
    const float* bfast= (const float*)d_in[15];
    const float* Wslow= (const float*)d_in[16];
    const float* bslow= (const float*)d_in[17];
    const float* Wsoma= (const float*)d_in[18];
    const float* bsoma= (const float*)d_in[19];
    const float* Wanc = (const float*)d_in[20];
    const float* banc = (const float*)d_in[21];
    const float* ascl = (const float*)d_in[22];
    const float* blend= (const float*)d_in[23];
    const float* lng  = (const float*)d_in[24];
    const float* lnb  = (const float*)d_in[25];
    float* out = (float*)d_out;

    float* xproj = symaddr(d_xproj);
    float* ctxg  = symaddr(d_ctxg);
    float* bfp   = symaddr(d_bf);
    float* bsp   = symaddr(d_bs);
    float* cfp   = symaddr(d_cf);
    float* csp   = symaddr(d_cs);
    float* gfr   = symaddr(d_gfr);
    float* gsr   = symaddr(d_gsr);
    float* somar = symaddr(d_somar);
    float* qp    = symaddr(d_q);
    float* kp    = symaddr(d_k);
    float* pm    = symaddr(d_pm);
    float* cg    = symaddr(d_cg);
    float* xa    = symaddr(d_xa);
    float* ancha = symaddr(d_ancha);
    float* delta = symaddr(d_delta);
    float* carG  = symaddr(d_carG);
    float* carF  = symaddr(d_carF);
    float* carS  = symaddr(d_carS);

    __nv_bfloat16* xS    = symaddrb(d_xS);
    __nv_bfloat16* ctxgS = symaddrb(d_ctxgS);
    __nv_bfloat16* cfS   = symaddrb(d_cfS);
    __nv_bfloat16* csS   = symaddrb(d_csS);
    __nv_bfloat16* WpS   = symaddrb(d_WpS);
    __nv_bfloat16* WxfS  = symaddrb(d_WxfS);
    __nv_bfloat16* WxsS  = symaddrb(d_WxsS);
    __nv_bfloat16* WcfS  = symaddrb(d_WcfS);
    __nv_bfloat16* WcsS  = symaddrb(d_WcsS);
    __nv_bfloat16* WfastS= symaddrb(d_WfastS);
    __nv_bfloat16* WslowS= symaddrb(d_WslowS);
    __nv_bfloat16* WsomaS= symaddrb(d_WsomaS);
    __nv_bfloat16* WqS   = symaddrb(d_WqS);
    __nv_bfloat16* WkS   = symaddrb(d_WkS);

    cudaFuncSetAttribute(mma_gemm, cudaFuncAttributeMaxDynamicSharedMemorySize, SMEMSZ);

    dim3 g6(6, MTOT/128);                 /* N=768 */
    dim3 g1(1, MTOT/128);                 /* N=96 padded to 128 */
    dim3 gema(Bb*NCH, Cc/256);

    /* split conversions: x + all weights */
    split_act<<<(MTOT*192+255)/256, 256>>>(x, xS);
    const int WG = (768*192+255)/256;
    split_w<<<WG,256>>>(Wp,    WpS,    768, 768);
    split_w<<<WG,256>>>(Wxf,   WxfS,   768, 768);
    split_w<<<WG,256>>>(Wxs,   WxsS,   768, 768);
    split_w<<<WG,256>>>(Wcf,   WcfS,   768, 768);
    split_w<<<WG,256>>>(Wcs,   WcsS,   768, 768);
    split_w<<<WG,256>>>(Wfast, WfastS, 768, 768);
    split_w<<<WG,256>>>(Wslow, WslowS, 768, 768);
    split_w<<<WG,256>>>(Wsoma, WsomaS, 768, 768);
    const int WGq = (128*192+255)/256;
    split_w<<<WGq,256>>>(Wq, WqS, DKk, 128);
    split_w<<<WGq,256>>>(Wk, WkS, DKk, 128);

    /* x_proj = tanh(x@Wp^T + bp) */
    mma_gemm<<<g6, 256, SMEMSZ>>>(xS, WpS, nullptr, nullptr, 1, bp, nullptr, xproj, Cc, 1);

    /* q, k */
    mma_gemm<<<g1, 256, SMEMSZ>>>(xS, WqS, nullptr, nullptr, 1, nullptr, nullptr, qp, DKk, 0);
    mma_gemm<<<g1, 256, SMEMSZ>>>(xS, WkS, nullptr, nullptr, 1, nullptr, nullptr, kp, DKk, 0);

    /* content gate cg */
    dim3 ga(Bb*(Tt/TTILE), NSB);
    attn_partmax<<<ga, 128>>>(qp, kp, pm);
    attn_reduce<<<(MTOT+255)/256, 256>>>(pm, cg);

    /* anchors -> delta (tiny, SIMT) */
    anchor_gather<<<(Bb*Nanc*Cc+255)/256, 256>>>(x, xa);
    gemm_k<<<dim3(Cc/128,1), 256>>>(xa, Wanc, Cc, banc, ancha, Bb*Nanc, Cc, 1);
    delta_k<<<(Bb*Cc+255)/256, 256>>>(ancha, ascl, delta);

    /* ctx_gate EMA on x */
    ema_p1<<<gema, 256>>>(x, ctxg, carG, tau_gate);
    ema_p2<<<(Bb*Cc+255)/256, 256>>>(carG, tau_gate);
    ema_p3<<<gema, 256>>>(ctxg, carG, tau_gate, nullptr, nullptr);
    split_act<<<(MTOT*192+255)/256, 256>>>(ctxg, ctxgS);

    /* bf = x_proj * sigmoid(x@Wxf^T + ctxg@Wcf^T + bxf); same for slow */
    mma_gemm<<<g6, 256, SMEMSZ>>>(xS, WxfS, ctxgS, WcfS, 2, bxf, xproj, bfp, Cc, 2);
    mma_gemm<<<g6, 256, SMEMSZ>>>(xS, WxsS, ctxgS, WcsS, 2, bxs, xproj, bsp, Cc, 2);

    /* ctx_fast / ctx_slow EMAs, with *cg + delta fused into phase 3 */
    ema_p1<<<gema, 256>>>(bfp, cfp, carF, tau_fast);
    ema_p1<<<gema, 256>>>(bsp, csp, carS, tau_slow);
    ema_p2<<<(Bb*Cc+255)/256, 256>>>(carF, tau_fast);
    ema_p2<<<(Bb*Cc+255)/256, 256>>>(carS, tau_slow);
    ema_p3<<<gema, 256>>>(cfp, carF, tau_fast, cg, delta);
    ema_p3<<<gema, 256>>>(csp, carS, tau_slow, cg, delta);

    split_act<<<(MTOT*192+255)/256, 256>>>(cfp, cfS);
    split_act<<<(MTOT*192+255)/256, 256>>>(csp, csS);

    /* gate pre-activations + soma pre-activation */
    mma_gemm<<<g6, 256, SMEMSZ>>>(cfS, WfastS, nullptr, nullptr, 1, bfast, nullptr, gfr,   Cc, 0);
    mma_gemm<<<g6, 256, SMEMSZ>>>(csS, WslowS, nullptr, nullptr, 1, bslow, nullptr, gsr,   Cc, 0);
    mma_gemm<<<g6, 256, SMEMSZ>>>(xS, WsomaS, nullptr, nullptr, 1, bsoma, nullptr, somar, Cc, 0);

    /* fused gates + layernorm */
    final_k<<<MTOT, 256>>>(gfr, gsr, somar, blend, lng, lnb, out);
}

// round 4
// speedup vs baseline: 2.7066x; 1.0554x over previous
#include <cuda_runtime.h>
#include <cuda_bf16.h>
#include <cstdint>
#include <math.h>

#define Bb 4
#define Tt 2048
#define Cc 768
#define DKk 96
#define Nanc 8
#define NCH 32
#define LCH 64          /* Tt / NCH */
#define NSB 8
#define SBLEN 256
#define TTILE 128
#define MTOT (Bb*Tt)    /* 8192 */

#define KSPLIT 2304     /* 3 * 768 split-bf16 expanded K */
#define BKs 32          /* K per stage */
#define TILE_BYTES (128*40*2)           /* 10240 (row stride 80B) */
#define STG_BYTES (2*TILE_BYTES)        /* A+B per stage: 20480 */
#define NSTG 3
#define SMEMSZ (NSTG*STG_BYTES + 256)   /* 61696 -> 2 CTAs/SM */

/* ------------ device scratch (static, no allocation) ------------- */
__device__ float d_xproj[MTOT*Cc];
__device__ float d_ctxg [MTOT*Cc];
__device__ float d_bf   [MTOT*Cc];
__device__ float d_bs   [MTOT*Cc];
__device__ float d_cf   [MTOT*Cc];
__device__ float d_cs   [MTOT*Cc];
__device__ float d_gfr  [MTOT*Cc];
__device__ float d_gsr  [MTOT*Cc];
__device__ float d_somar[MTOT*Cc];
__device__ float d_qk   [MTOT*256];
__device__ float d_pm   [MTOT*NSB];
__device__ float d_cg   [MTOT];
__device__ float d_xa   [Bb*Nanc*Cc];
__device__ float d_ancha[Bb*Nanc*Cc];
__device__ float d_delta[Bb*Cc];
__device__ float d_carG [Bb*NCH*Cc];
__device__ float d_carF [Bb*NCH*Cc];
__device__ float d_carS [Bb*NCH*Cc];

/* split-bf16 expanded buffers */
__device__ __nv_bfloat16 d_xS   [(long)MTOT*KSPLIT];
__device__ __nv_bfloat16 d_ctxgS[(long)MTOT*KSPLIT];
__device__ __nv_bfloat16 d_cfS  [(long)MTOT*KSPLIT];
__device__ __nv_bfloat16 d_csS  [(long)MTOT*KSPLIT];
__device__ __nv_bfloat16 d_WpS   [768*KSPLIT];
__device__ __nv_bfloat16 d_WxfS  [768*KSPLIT];
__device__ __nv_bfloat16 d_WxsS  [768*KSPLIT];
__device__ __nv_bfloat16 d_WcfS  [768*KSPLIT];
__device__ __nv_bfloat16 d_WcsS  [768*KSPLIT];
__device__ __nv_bfloat16 d_WfastS[768*KSPLIT];
__device__ __nv_bfloat16 d_WslowS[768*KSPLIT];
__device__ __nv_bfloat16 d_WsomaS[768*KSPLIT];
__device__ __nv_bfloat16 d_WqkS  [256*KSPLIT];

/* ---------------- helpers ---------------- */
__device__ __forceinline__ float alpha_of(const float* tau){
    float t = *tau;
    float sp = (t > 20.f) ? t : log1pf(expf(t));
    return expf(-sp);
}
__device__ __forceinline__ float sigmoidf_(float v){ return 1.f/(1.f+expf(-v)); }

__device__ __forceinline__ uint32_t smem_u32(const void* p){
    uint32_t a;
    asm("{ .reg .u64 t; cvta.to.shared.u64 t, %1; cvt.u32.u64 %0, t; }" : "=r"(a) : "l"(p));
    return a;
}

__device__ __forceinline__ void cp_async16(uint32_t dst, const void* src){
    asm volatile("cp.async.cg.shared.global [%0], [%1], 16;" :: "r"(dst), "l"(src));
}
__device__ __forceinline__ void cp_commit(){ asm volatile("cp.async.commit_group;" ::: "memory"); }
template<int N> __device__ __forceinline__ void cp_wait(){ asm volatile("cp.async.wait_group %0;" :: "n"(N) : "memory"); }

__device__ __forceinline__ void ldm_x4(uint32_t addr, uint32_t& r0, uint32_t& r1, uint32_t& r2, uint32_t& r3){
    asm volatile("ldmatrix.sync.aligned.m8n8.x4.shared.b16 {%0,%1,%2,%3}, [%4];"
        : "=r"(r0), "=r"(r1), "=r"(r2), "=r"(r3) : "r"(addr));
}
__device__ __forceinline__ void mma16816(float& c0, float& c1, float& c2, float& c3,
                                         uint32_t a0, uint32_t a1, uint32_t a2, uint32_t a3,
                                         uint32_t b0, uint32_t b1){
    asm volatile("mma.sync.aligned.m16n8k16.row.col.f32.bf16.bf16.f32 "
        "{%0,%1,%2,%3}, {%4,%5,%6,%7}, {%8,%9}, {%0,%1,%2,%3};"
        : "+f"(c0), "+f"(c1), "+f"(c2), "+f"(c3)
        : "r"(a0), "r"(a1), "r"(a2), "r"(a3), "r"(b0), "r"(b1));
}

/* ---------------- split-bf16 conversion ---------------- */
__device__ __forceinline__ void split4(float4 v,
        __nv_bfloat162& hA, __nv_bfloat162& hB, __nv_bfloat162& lA, __nv_bfloat162& lB)
{
    __nv_bfloat16 h0=__float2bfloat16(v.x), h1=__float2bfloat16(v.y),
                  h2=__float2bfloat16(v.z), h3=__float2bfloat16(v.w);
    lA.x=__float2bfloat16(v.x-__bfloat162float(h0));
    lA.y=__float2bfloat16(v.y-__bfloat162float(h1));
    lB.x=__float2bfloat16(v.z-__bfloat162float(h2));
    lB.y=__float2bfloat16(v.w-__bfloat162float(h3));
    hA.x=h0; hA.y=h1; hB.x=h2; hB.y=h3;
}

__global__ void split_act(const float* __restrict__ in, __nv_bfloat16* __restrict__ out)
{
    long i = (long)blockIdx.x*256 + threadIdx.x;  /* over MTOT*192 float4 groups */
    if (i >= (long)MTOT*192) return;
    long r = i / 192; int c4 = (int)(i % 192);
    float4 v = *(const float4*)(in + r*768 + c4*4);
    __nv_bfloat162 hA,hB,lA,lB; split4(v,hA,hB,lA,lB);
    __nv_bfloat162* o0 = (__nv_bfloat162*)(out + r*KSPLIT + c4*4);
    __nv_bfloat162* o1 = (__nv_bfloat162*)(out + r*KSPLIT + 768 + c4*4);
    __nv_bfloat162* o2 = (__nv_bfloat162*)(out + r*KSPLIT + 1536 + c4*4);
    o0[0]=hA; o0[1]=hB;         /* hi */
    o1[0]=hA; o1[1]=hB;         /* hi */
    o2[0]=lA; o2[1]=lB;         /* lo */
}

/* weights: layout [hi | lo | hi] so A[hi|hi|lo] x W[hi|lo|hi] = hh+hl+lh */
struct WSplitJobs {
    const float* src[10];
    __nv_bfloat16* dst[10];
    int nsrc[10];
    int npad[10];
};
__global__ void split_w_all(WSplitJobs J)
{
    int j = blockIdx.y;
    long i = (long)blockIdx.x*256 + threadIdx.x;
    int npad = J.npad[j];
    if (i >= (long)npad*192) return;
    int r = (int)(i / 192); int c4 = (int)(i % 192);
    float4 v = make_float4(0.f,0.f,0.f,0.f);
    if (r < J.nsrc[j]) v = *(const float4*)(J.src[j] + (long)r*768 + c4*4);
    __nv_bfloat162 hA,hB,lA,lB; split4(v,hA,hB,lA,lB);
    __nv_bfloat16* out = J.dst[j];
    __nv_bfloat162* o0 = (__nv_bfloat162*)(out + (long)r*KSPLIT + c4*4);
    __nv_bfloat162* o1 = (__nv_bfloat162*)(out + (long)r*KSPLIT + 768 + c4*4);
    __nv_bfloat162* o2 = (__nv_bfloat162*)(out + (long)r*KSPLIT + 1536 + c4*4);
    o0[0]=hA; o0[1]=hB;         /* hi */
    o1[0]=lA; o1[1]=lB;         /* lo */
    o2[0]=hA; o2[1]=hB;         /* hi */
}

/* ---------------- batched mma.sync GEMM ----------------
   per z-job: out[8192, Nout] = epi( sum_seg A_seg@B_seg^T + bias )
   CTA tile 128x128, BK=32, 8 warps (4m x 2n), warp tile 32x64.
   epi: 0 none, 1 tanh, 2 sigmoid(acc)*mult                       */
struct GemmJobs {
    const __nv_bfloat16 *A1[3], *B1[3], *A2[3], *B2[3];
    const float *bias[3], *mult[3];
    float *out[3];
    int nseg[3], Nout[3], ncol[3], epi[3];
};

__device__ __forceinline__ void load_stage(const __nv_bfloat16* __restrict__ A,
                                           const __nv_bfloat16* __restrict__ Bp,
                                           int kofs, uint32_t sbuf, int tid)
{
    uint32_t sA = sbuf, sB = sbuf + TILE_BYTES;
#pragma unroll
    for (int it = 0; it < 2; it++){        /* A: 128 rows x 4 chunks of 16B */
        int ci = it*256 + tid;
        int row = ci >> 2, c = ci & 3;
        cp_async16(sA + row*80 + c*16, A + (long)row*KSPLIT + kofs + c*8);
    }
#pragma unroll
    for (int it = 0; it < 2; it++){        /* B: 128 rows x 4 chunks */
        int ci = it*256 + tid;
        int row = ci >> 2, c = ci & 3;
        cp_async16(sB + row*80 + c*16, Bp + (long)row*KSPLIT + kofs + c*8);
    }
    cp_commit();
}

__global__ void __launch_bounds__(256, 2)
mma_gemm(GemmJobs J)
{
    extern __shared__ char dyn[];
    const int jz = blockIdx.z;
    if ((int)blockIdx.x >= J.ncol[jz]) return;
    const int tid  = threadIdx.x;
    const int lane = tid & 31;
    const int wid  = tid >> 5;
    const int wm   = wid & 3;        /* 0..3 : m */
    const int wn   = wid >> 2;       /* 0..1 : n */
    const int row0 = blockIdx.y * 128;
    const int col0 = blockIdx.x * 128;
    const int Nout = J.Nout[jz];
    const int epi  = J.epi[jz];
    const float* bias = J.bias[jz];
    const float* mult = J.mult[jz];
    float* out = J.out[jz];
    uint32_t sbase = (smem_u32(dyn) + 127u) & ~127u;

    const __nv_bfloat16* Aseg[2];
    const __nv_bfloat16* Bseg[2];
    Aseg[0] = J.A1[jz] + (long)row0*KSPLIT;
    Bseg[0] = J.B1[jz] + (long)col0*KSPLIT;
    Aseg[1] = J.A2[jz] ? (J.A2[jz] + (long)row0*KSPLIT) : Aseg[0];
    Bseg[1] = J.B2[jz] ? (J.B2[jz] + (long)col0*KSPLIT) : Bseg[0];
    const int SPS = KSPLIT / BKs;            /* 72 stages per segment */
    const int S = SPS * J.nseg[jz];

    float acc[2][8][4];
#pragma unroll
    for (int i=0;i<2;i++)
#pragma unroll
        for (int j=0;j<8;j++)
#pragma unroll
            for (int r=0;r<4;r++) acc[i][j][r]=0.f;

    int aM = lane & 15;
    int aK = (lane >> 4) * 8;
    int bN = ((lane >> 4) & 1)*8 + (lane & 7);
    int bK = ((lane >> 3) & 1)*8;

    /* prologue: stages 0..NSTG-2 */
#pragma unroll
    for (int p = 0; p < NSTG-1; p++)
        load_stage(Aseg[0], Bseg[0], p*BKs, sbase + p*STG_BYTES, tid);

    for (int s = 0; s < S; s++){
        cp_wait<NSTG-2>();
        __syncthreads();
        uint32_t sA = sbase + (s % NSTG)*STG_BYTES;
        uint32_t sB = sA + TILE_BYTES;
#pragma unroll
        for (int ks = 0; ks < 2; ks++){
            int k0 = ks*16;
            uint32_t a[2][4];
#pragma unroll
            for (int i=0;i<2;i++){
                uint32_t ad = sA + (uint32_t)(wm*32 + i*16 + aM)*80 + (uint32_t)(k0 + aK)*2;
                ldm_x4(ad, a[i][0], a[i][1], a[i][2], a[i][3]);
            }
            uint32_t b[8][2];
#pragma unroll
            for (int jj=0;jj<4;jj++){
                uint32_t bd = sB + (uint32_t)(wn*64 + jj*16 + bN)*80 + (uint32_t)(k0 + bK)*2;
                uint32_t r0,r1,r2,r3;
                ldm_x4(bd, r0, r1, r2, r3);
                b[2*jj][0]=r0; b[2*jj][1]=r1; b[2*jj+1][0]=r2; b[2*jj+1][1]=r3;
            }
#pragma unroll
            for (int i=0;i<2;i++)
#pragma unroll
                for (int j=0;j<8;j++)
                    mma16816(acc[i][j][0], acc[i][j][1], acc[i][j][2], acc[i][j][3],
                             a[i][0], a[i][1], a[i][2], a[i][3], b[j][0], b[j][1]);
        }
        int nl = s + NSTG - 1;
        if (nl < S){
            int seg = (nl >= SPS) ? 1 : 0;
            int ko  = (nl - seg*SPS) * BKs;
            load_stage(Aseg[seg], Bseg[seg], ko, sbase + (nl % NSTG)*STG_BYTES, tid);
        }
    }

    /* epilogue */
#pragma unroll
    for (int i=0;i<2;i++){
        int rlo = row0 + wm*32 + i*16 + (lane >> 2);
#pragma unroll
        for (int j=0;j<8;j++){
            int c = col0 + wn*64 + j*8 + (lane & 3)*2;
            if (c >= Nout) continue;
#pragma unroll
            for (int h=0;h<2;h++){
                long r = rlo + h*8;
                float v0 = acc[i][j][2*h], v1 = acc[i][j][2*h+1];
                if (bias){ v0 += bias[c]; v1 += bias[c+1]; }
                if (epi == 1){ v0 = tanhf(v0); v1 = tanhf(v1); }
                else if (epi == 2){
                    float m0 = mult[r*768 + c], m1 = mult[r*768 + c + 1];
                    v0 = m0 * sigmoidf_(v0); v1 = m1 * sigmoidf_(v1);
                }
                float2 st; st.x = v0; st.y = v1;
                *(float2*)(out + r*(long)Nout + c) = st;
            }
        }
    }
}

/* ---------------- SIMT GEMM (tiny anchor matmul) ---------------- */
__global__ void __launch_bounds__(256)
gemm_k(const float* __restrict__ A1, const float* __restrict__ W1, int K1,
       const float* __restrict__ bias,
       float* __restrict__ out, int M, int N, int epi)
{
    __shared__ float As[8][128];
    __shared__ float Bs[8][128];
    int tid  = threadIdx.x;
    int row0 = blockIdx.y * 128;
    int col0 = blockIdx.x * 128;
    int tx = tid & 15, ty = tid >> 4;
    float acc[8][8];
#pragma unroll
    for (int i=0;i<8;i++)
#pragma unroll
        for (int j=0;j<8;j++) acc[i][j]=0.f;

    int lr = tid >> 1;
    int lc = (tid & 1) * 4;

    for (int k0 = 0; k0 < K1; k0 += 8){
        float4 av = make_float4(0,0,0,0), wv = make_float4(0,0,0,0);
        int gr = row0 + lr;
        if (gr < M) av = *(const float4*)(A1 + (long)gr*K1 + k0 + lc);
        int gc = col0 + lr;
        if (gc < N) wv = *(const float4*)(W1 + (long)gc*K1 + k0 + lc);
        As[lc+0][lr]=av.x; As[lc+1][lr]=av.y; As[lc+2][lr]=av.z; As[lc+3][lr]=av.w;
        Bs[lc+0][lr]=wv.x; Bs[lc+1][lr]=wv.y; Bs[lc+2][lr]=wv.z; Bs[lc+3][lr]=wv.w;
        __syncthreads();
#pragma unroll
        for (int kk=0; kk<8; kk++){
            float4 a0 = *(const float4*)&As[kk][ty*8];
            float4 a1 = *(const float4*)&As[kk][ty*8+4];
            float4 b0 = *(const float4*)&Bs[kk][tx*8];
            float4 b1 = *(const float4*)&Bs[kk][tx*8+4];
            float ar[8]={a0.x,a0.y,a0.z,a0.w,a1.x,a1.y,a1.z,a1.w};
            float br[8]={b0.x,b0.y,b0.z,b0.w,b1.x,b1.y,b1.z,b1.w};
#pragma unroll
            for (int i=0;i<8;i++)
#pragma unroll
                for (int j=0;j<8;j++)
                    acc[i][j] += ar[i]*br[j];
        }
        __syncthreads();
    }
#pragma unroll
    for (int i=0;i<8;i++){
        int r = row0 + ty*8 + i;
        if (r >= M) continue;
#pragma unroll
        for (int j=0;j<8;j++){
            int c = col0 + tx*8 + j;
            if (c >= N) continue;
            float v = acc[i][j];
            if (bias) v += bias[c];
            if (epi == 1) v = tanhf(v);
            out[(long)r*N + c] = v;
        }
    }
}

/* ---------------- EMA: 3-phase chunked scan (z-batched jobs) ---------------- */
struct EP {
    const float* in;        /* p1 input */
    float* h;               /* p1 output / p3 input (chunk-local scan) */
    float* car;             /* carries */
    const float* tau;
    const float* cg;        /* optional */
    const float* delta;     /* optional */
    __nv_bfloat16* outS;    /* p3 split output */
};
struct EPs { EP j[2]; };

__global__ void ema_p1(EPs E)
{
    const EP& e = E.j[blockIdx.z];
    int c  = blockIdx.y*256 + threadIdx.x;
    int b  = blockIdx.x / NCH, ch = blockIdx.x % NCH;
    float alpha = alpha_of(e.tau);
    const float* p  = e.in + ((long)b*Tt + ch*LCH)*Cc + c;
    float*       po = e.h  + ((long)b*Tt + ch*LCH)*Cc + c;
    float h = 0.f;
#pragma unroll 8
    for (int t=0; t<LCH; t++){
        h = alpha*h + p[(long)t*Cc];
        po[(long)t*Cc] = h;
    }
    e.car[((long)b*NCH + ch)*Cc + c] = h;
}

__global__ void ema_p2(EPs E)
{
    const EP& e = E.j[blockIdx.z];
    int i = blockIdx.x*256 + threadIdx.x;
    if (i >= Bb*Cc) return;
    int b = i / Cc, c = i % Cc;
    float alpha = alpha_of(e.tau);
    float aL = powf(alpha, (float)LCH);
    float H = 0.f;
    for (int ch=0; ch<NCH; ch++){
        float* pc = &e.car[((long)b*NCH+ch)*Cc + c];
        float cv = *pc;
        *pc = H;
        H = aL*H + cv;
    }
}

/* phase 3: inject carry, apply optional cg*+delta, emit split-bf16 [hi|hi|lo] */
__global__ void ema_p3s(EPs E)
{
    const EP& e = E.j[blockIdx.z];
    int c  = blockIdx.y*256 + threadIdx.x;
    int b  = blockIdx.x / NCH, ch = blockIdx.x % NCH;
    float alpha = alpha_of(e.tau);
    float P = e.car[((long)b*NCH+ch)*Cc + c];
    const float* p = e.h + ((long)b*Tt + ch*LCH)*Cc + c;
    const float* cgp = e.cg ? (e.cg + (long)b*Tt + ch*LCH) : nullptr;
    float dl = e.delta ? e.delta[(long)b*Cc + c] : 0.f;
    __nv_bfloat16* oS = e.outS + ((long)b*Tt + ch*LCH)*KSPLIT + c;
    float ap = alpha;
#pragma unroll 4
    for (int t=0; t<LCH; t++){
        float v = p[(long)t*Cc] + ap*P;
        if (cgp) v = v*cgp[t] + dl;
        __nv_bfloat16 h = __float2bfloat16(v);
        __nv_bfloat16 l = __float2bfloat16(v - __bfloat162float(h));
        oS[(long)t*KSPLIT]        = h;
        oS[(long)t*KSPLIT + 768]  = h;
        oS[(long)t*KSPLIT + 1536] = l;
        ap *= alpha;
    }
}

/* ---------------- causal max-score attention (q/k packed stride 256) ------- */
__global__ void __launch_bounds__(128)
attn_partmax(const float* __restrict__ qk, float* __restrict__ pm)
{
    const int nt = Tt / TTILE;
    int b  = blockIdx.x / nt, tt = blockIdx.x % nt;
    int sb = blockIdx.y;
    int t  = tt*TTILE + threadIdx.x;
    int tmax = tt*TTILE + TTILE - 1;
    int s_begin = sb * SBLEN;
    float m = -INFINITY;
    if (s_begin <= tmax){
        float qr[DKk];
        const float4* qp = (const float4*)(qk + ((long)b*Tt + t)*256);
#pragma unroll
        for (int i=0;i<DKk/4;i++){
            float4 v = qp[i];
            qr[4*i]=v.x; qr[4*i+1]=v.y; qr[4*i+2]=v.z; qr[4*i+3]=v.w;
        }
        __shared__ float ksh[64*DKk];
        int s_end = min(s_begin + SBLEN, tmax + 1);
        for (int s0 = s_begin; s0 < s_end; s0 += 64){
            __syncthreads();
            const float4* kp = (const float4*)(qk + (long)(b*Tt + s0)*256) + 32;
            float4* kd = (float4*)ksh;
            for (int i = threadIdx.x; i < 64*24; i += 128){
                int row = i / 24, cc = i % 24;
                kd[row*24 + cc] = kp[(long)row*64 + cc];
            }
            __syncthreads();
            int ssmax = min(64, t - s0 + 1);
            for (int ss=0; ss<ssmax; ss++){
                const float* kr = &ksh[ss*DKk];
                float a0=0.f,a1=0.f,a2=0.f,a3=0.f;
#pragma unroll
                for (int d=0; d<DKk; d+=16){
                    float4 k0 = *(const float4*)&kr[d];
                    float4 k1 = *(const float4*)&kr[d+4];
                    float4 k2 = *(const float4*)&kr[d+8];
                    float4 k3 = *(const float4*)&kr[d+12];
                    a0 += qr[d+0]*k0.x + qr[d+1]*k0.y + qr[d+2]*k0.z + qr[d+3]*k0.w;
                    a1 += qr[d+4]*k1.x + qr[d+5]*k1.y + qr[d+6]*k1.z + qr[d+7]*k1.w;
                    a2 += qr[d+8]*k2.x + qr[d+9]*k2.y + qr[d+10]*k2.z + qr[d+11]*k2.w;
                    a3 += qr[d+12]*k3.x + qr[d+13]*k3.y + qr[d+14]*k3.z + qr[d+15]*k3.w;
                }
                m = fmaxf(m, (a0+a1)+(a2+a3));
            }
        }
    }
    pm[((long)b*Tt + t)*NSB + sb] = m;
}

__global__ void attn_reduce(const float* __restrict__ pm, float* __restrict__ cgout)
{
    int i = blockIdx.x*256 + threadIdx.x;
    if (i >= MTOT) return;
    float m = pm[(long)i*NSB];
#pragma unroll
    for (int j=1;j<NSB;j++) m = fmaxf(m, pm[(long)i*NSB + j]);
    m *= rsqrtf((float)DKk);
    cgout[i] = sigmoidf_(m);
}

/* ---------------- anchors ---------------- */
__global__ void anchor_gather(const float* __restrict__ x, float* __restrict__ xa)
{
    int i = blockIdx.x*256 + threadIdx.x;
    if (i >= Bb*Nanc*Cc) return;
    int c = i % Cc;
    int n = (i / Cc) % Nanc;
    int b = i / (Cc*Nanc);
    int pos = n * (Tt / Nanc);
    if (pos > Tt-1) pos = Tt-1;
    xa[i] = x[((long)b*Tt + pos)*Cc + c];
}

__global__ void delta_k(const float* __restrict__ ancha, const float* __restrict__ scales,
                        float* __restrict__ delta)
{
    int i = blockIdx.x*256 + threadIdx.x;
    if (i >= Bb*Cc) return;
    int b = i / Cc, c = i % Cc;
    float s = 0.f;
#pragma unroll
    for (int n=0;n<Nanc;n++){
        float sg = sigmoidf_(scales[n]);
        s += sg * ancha[((long)b*Nanc + n)*Cc + c];
    }
    delta[i] = s;
}

/* ---------------- final gate + layernorm ---------------- */
__global__ void __launch_bounds__(256)
final_k(const float* __restrict__ gfr, const float* __restrict__ gsr,
        const float* __restrict__ somar, const float* __restrict__ blend,
        const float* __restrict__ lng, const float* __restrict__ lnb,
        float* __restrict__ out)
{
    long row = blockIdx.x;
    int tid = threadIdx.x;
    float bl = sigmoidf_(blend[0]);
    float y[3]; float s = 0.f, sq = 0.f;
#pragma unroll
    for (int j=0;j<3;j++){
        int c = tid + j*256;
        long idx = row*Cc + c;
        float f  = sigmoidf_(gfr[idx]);
        float g2 = sigmoidf_(gsr[idx]);
        float gate = f + bl*(g2 - f);
        float v = tanhf(somar[idx]) * gate;
        y[j] = v; s += v; sq += v*v;
    }
    __shared__ float rs[8], rq[8];
#pragma unroll
    for (int o=16;o>0;o>>=1){
        s  += __shfl_xor_sync(0xffffffffu, s,  o);
        sq += __shfl_xor_sync(0xffffffffu, sq, o);
    }
    if ((tid & 31) == 0){ rs[tid>>5] = s; rq[tid>>5] = sq; }
    __syncthreads();
    if (tid == 0){
        float ts=0.f, tq=0.f;
#pragma unroll
        for (int w=0;w<8;w++){ ts += rs[w]; tq += rq[w]; }
        rs[0] = ts; rq[0] = tq;
    }
    __syncthreads();
    float mu  = rs[0] / Cc;
    float var = rq[0] / Cc - mu*mu;
    float inv = rsqrtf(var + 1e-5f);
#pragma unroll
    for (int j=0;j<3;j++){
        int c = tid + j*256;
        long idx = row*Cc + c;
        out[idx] = (y[j]-mu)*inv*lng[c] + lnb[c];
    }
}

/* ---------------- launch ---------------- */
static float* symaddr(const void* sym){
    void* p = nullptr;
    cudaGetSymbolAddress(&p, sym);
    return (float*)p;
}
static __nv_bfloat16* symaddrb(const void* sym){
    void* p = nullptr;
    cudaGetSymbolAddress(&p, sym);
    return (__nv_bfloat16*)p;
}

extern "C" void kernel_launch(void* const* d_in, const int* in_sizes, int n_in,
                              void* d_out, int out_size)
{
    const float* x        = (const float*)d_in[0];
    const float* tau_gate = (const float*)d_in[1];
    const float* tau_fast = (const float*)d_in[2];
    const float* tau_slow = (const float*)d_in[3];
    const float* Wp   = (const float*)d_in[4];
    const float* bp   = (const float*)d_in[5];
    const float* Wxf  = (const float*)d_in[6];
    const float* bxf  = (const float*)d_in[7];
    const float* Wxs  = (const float*)d_in[8];
    const float* bxs  = (const float*)d_in[9];
    const float* Wcf  = (const float*)d_in[10];
    const float* Wcs  = (const float*)d_in[11];
    const float* Wq   = (const float*)d_in[12];
    const float* Wk   = (const float*)d_in[13];
    const float* Wfast= (const float*)d_in[14];
    const float* bfast= (const float*)d_in[15];
    const float* Wslow= (const float*)d_in[16];
    const float* bslow= (const float*)d_in[17];
    const float* Wsoma= (const float*)d_in[18];
    const float* bsoma= (const float*)d_in[19];
    const float* Wanc = (const float*)d_in[20];
    const float* banc = (const float*)d_in[21];
    const float* ascl = (const float*)d_in[22];
    const float* blend= (const float*)d_in[23];
    const float* lng  = (const float*)d_in[24];
    const float* lnb  = (const float*)d_in[25];
    float* out = (float*)d_out;

    float* xproj = symaddr(d_xproj);
    float* ctxg  = symaddr(d_ctxg);
    float* bfp   = symaddr(d_bf);
    float* bsp   = symaddr(d_bs);
    float* cfp   = symaddr(d_cf);
    float* csp   = symaddr(d_cs);
    float* gfr   = symaddr(d_gfr);
    float* gsr   = symaddr(d_gsr);
    float* somar = symaddr(d_somar);
    float* qk    = symaddr(d_qk);
    float* pm    = symaddr(d_pm);
    float* cg    = symaddr(d_cg);
    float* xa    = symaddr(d_xa);
    float* ancha = symaddr(d_ancha);
    float* delta = symaddr(d_delta);
    float* carG  = symaddr(d_carG);
    float* carF  = symaddr(d_carF);
    float* carS  = symaddr(d_carS);

    __nv_bfloat16* xS    = symaddrb(d_xS);
    __nv_bfloat16* ctxgS = symaddrb(d_ctxgS);
    __nv_bfloat16* cfS   = symaddrb(d_cfS);
    __nv_bfloat16* csS   = symaddrb(d_csS);
    __nv_bfloat16* WpS   = symaddrb(d_WpS);
    __nv_bfloat16* WxfS  = symaddrb(d_WxfS);
    __nv_bfloat16* WxsS  = symaddrb(d_WxsS);
    __nv_bfloat16* WcfS  = symaddrb(d_WcfS);
    __nv_bfloat16* WcsS  = symaddrb(d_WcsS);
    __nv_bfloat16* WfastS= symaddrb(d_WfastS);
    __nv_bfloat16* WslowS= symaddrb(d_WslowS);
    __nv_bfloat16* WsomaS= symaddrb(d_WsomaS);
    __nv_bfloat16* WqkS  = symaddrb(d_WqkS);

    cudaFuncSetAttribute(mma_gemm, cudaFuncAttributeMaxDynamicSharedMemorySize, SMEMSZ);

    dim3 gema(Bb*NCH, Cc/256, 1);
    dim3 gema2(Bb*NCH, Cc/256, 2);

    /* 1: x split */
    split_act<<<(MTOT*192+255)/256, 256>>>(x, xS);

    /* 2: all weight splits in one launch */
    {
        WSplitJobs WJ;
        const float* srcs[10] = {Wp,Wxf,Wxs,Wcf,Wcs,Wfast,Wslow,Wsoma,Wq,Wk};
        __nv_bfloat16* dsts[10] = {WpS,WxfS,WxsS,WcfS,WcsS,WfastS,WslowS,WsomaS,
                                   WqkS, WqkS + (long)128*KSPLIT};
        int ns[10] = {768,768,768,768,768,768,768,768,DKk,DKk};
        int np[10] = {768,768,768,768,768,768,768,768,128,128};
        for (int i=0;i<10;i++){ WJ.src[i]=srcs[i]; WJ.dst[i]=dsts[i]; WJ.nsrc[i]=ns[i]; WJ.npad[i]=np[i]; }
        split_w_all<<<dim3(576,10), 256>>>(WJ);
    }

    /* 3: ctx_gate EMA on x -> ctxgS */
    {
        EPs E; E.j[0] = {x, ctxg, carG, tau_gate, nullptr, nullptr, ctxgS}; E.j[1] = E.j[0];
        ema_p1<<<gema, 256>>>(E);
        ema_p2<<<dim3((Bb*Cc+255)/256,1,1), 256>>>(E);
        ema_p3s<<<gema, 256>>>(E);
    }

    /* 4: batch1 gemm: xproj (tanh) + qk */
    {
        GemmJobs G = {};
        G.A1[0]=xS;  G.B1[0]=WpS;  G.nseg[0]=1; G.bias[0]=bp;     G.out[0]=xproj; G.Nout[0]=768; G.ncol[0]=6; G.epi[0]=1;
        G.A1[1]=xS;  G.B1[1]=WqkS; G.nseg[1]=1; G.bias[1]=nullptr;G.out[1]=qk;    G.Nout[1]=256; G.ncol[1]=2; G.epi[1]=0;
        mma_gemm<<<dim3(6, MTOT/128, 2), 256, SMEMSZ>>>(G);
    }

    /* 5: content gate cg */
    attn_partmax<<<dim3(Bb*(Tt/TTILE), NSB), 128>>>(qk, pm);
    attn_reduce<<<(MTOT+255)/256, 256>>>(pm, cg);

    /* 6: anchors -> delta (tiny, SIMT) */
    anchor_gather<<<(Bb*Nanc*Cc+255)/256, 256>>>(x, xa);
    gemm_k<<<dim3(Cc/128,1), 256>>>(xa, Wanc, Cc, banc, ancha, Bb*Nanc, Cc, 1);
    delta_k<<<(Bb*Cc+255)/256, 256>>>(ancha, ascl, delta);

    /* 7: batch2 gemm: bf, bs (sigmoid * xproj) */
    {
        GemmJobs G = {};
        G.A1[0]=xS; G.B1[0]=WxfS; G.A2[0]=ctxgS; G.B2[0]=WcfS; G.nseg[0]=2;
        G.bias[0]=bxf; G.mult[0]=xproj; G.out[0]=bfp; G.Nout[0]=768; G.ncol[0]=6; G.epi[0]=2;
        G.A1[1]=xS; G.B1[1]=WxsS; G.A2[1]=ctxgS; G.B2[1]=WcsS; G.nseg[1]=2;
        G.bias[1]=bxs; G.mult[1]=xproj; G.out[1]=bsp; G.Nout[1]=768; G.ncol[1]=6; G.epi[1]=2;
        mma_gemm<<<dim3(6, MTOT/128, 2), 256, SMEMSZ>>>(G);
    }

    /* 8: fast/slow EMAs (z-batched), phase3 fuses *cg + delta and split output */
    {
        EPs E;
        E.j[0] = {bfp, cfp, carF, tau_fast, cg, delta, cfS};
        E.j[1] = {bsp, csp, carS, tau_slow, cg, delta, csS};
        ema_p1<<<gema2, 256>>>(E);
        ema_p2<<<dim3((Bb*Cc+255)/256,1,2), 256>>>(E);
        ema_p3s<<<gema2, 256>>>(E);
    }

    /* 9: batch3 gemm: gfr, gsr, somar */
    {
        GemmJobs G = {};
        G.A1[0]=cfS; G.B1[0]=WfastS; G.nseg[0]=1; G.bias[0]=bfast; G.out[0]=gfr;   G.Nout[0]=768; G.ncol[0]=6; G.epi[0]=0;
        G.A1[1]=csS; G.B1[1]=WslowS; G.nseg[1]=1; G.bias[1]=bslow; G.out[1]=gsr;   G.Nout[1]=768; G.ncol[1]=6; G.epi[1]=0;
        G.A1[2]=xS;  G.B1[2]=WsomaS; G.nseg[2]=1; G.bias[2]=bsoma; G.out[2]=somar; G.Nout[2]=768; G.ncol[2]=6; G.epi[2]=0;
        mma_gemm<<<dim3(6, MTOT/128, 3), 256, SMEMSZ>>>(G);
    }

    /* 10: fused gates + layernorm */
    final_k<<<MTOT, 256>>>(gfr, gsr, somar, blend, lng, lnb, out);
}

// round 5
// speedup vs baseline: 3.3966x; 1.2549x over previous
#include <cuda_runtime.h>
#include <cuda_fp16.h>
#include <cstdint>
#include <math.h>

#define Bb 4
#define Tt 2048
#define Cc 768
#define DKk 96
#define Nanc 8
#define NCH 32
#define LCH 64          /* Tt / NCH */
#define NSB 8
#define SBLEN 256
#define TTILE 128
#define MTOT (Bb*Tt)    /* 8192 */

#define KSPLIT 1536     /* 2 * 768 split-fp16 expanded K */
#define BKs 32          /* K per stage */
#define TILE_BYTES (128*40*2)           /* 10240 (row stride 80B) */
#define STG_BYTES (2*TILE_BYTES)        /* A+B per stage: 20480 */
#define NSTG 3
#define SMEMSZ (NSTG*STG_BYTES + 256)   /* 61696 -> 2 CTAs/SM */

/* ------------ device scratch (static, no allocation) ------------- */
__device__ float d_xproj[MTOT*Cc];
__device__ float d_ctxg [MTOT*Cc];
__device__ float d_bf   [MTOT*Cc];
__device__ float d_bs   [MTOT*Cc];
__device__ float d_cf   [MTOT*Cc];
__device__ float d_cs   [MTOT*Cc];
__device__ float d_gfr  [MTOT*Cc];
__device__ float d_gsr  [MTOT*Cc];
__device__ float d_somar[MTOT*Cc];
__device__ float d_qk   [MTOT*256];
__device__ float d_pm   [MTOT*NSB];
__device__ float d_cg   [MTOT];
__device__ float d_xa   [Bb*Nanc*Cc];
__device__ float d_ancha[Bb*Nanc*Cc];
__device__ float d_delta[Bb*Cc];
__device__ float d_carG [Bb*NCH*Cc];
__device__ float d_carF [Bb*NCH*Cc];
__device__ float d_carS [Bb*NCH*Cc];

/* split-fp16 expanded buffers: activations [hi|lo], weights [hi|hi] */
__device__ __half d_xS   [(long)MTOT*KSPLIT];
__device__ __half d_ctxgS[(long)MTOT*KSPLIT];
__device__ __half d_cfS  [(long)MTOT*KSPLIT];
__device__ __half d_csS  [(long)MTOT*KSPLIT];
__device__ __half d_WpS   [768*KSPLIT];
__device__ __half d_WxfS  [768*KSPLIT];
__device__ __half d_WxsS  [768*KSPLIT];
__device__ __half d_WcfS  [768*KSPLIT];
__device__ __half d_WcsS  [768*KSPLIT];
__device__ __half d_WfastS[768*KSPLIT];
__device__ __half d_WslowS[768*KSPLIT];
__device__ __half d_WsomaS[768*KSPLIT];
__device__ __half d_WqkS  [256*KSPLIT];

/* ---------------- helpers ---------------- */
__device__ __forceinline__ float alpha_of(const float* tau){
    float t = *tau;
    float sp = (t > 20.f) ? t : log1pf(expf(t));
    return expf(-sp);
}
__device__ __forceinline__ float sigmoidf_(float v){ return 1.f/(1.f+expf(-v)); }

__device__ __forceinline__ uint32_t smem_u32(const void* p){
    uint32_t a;
    asm("{ .reg .u64 t; cvta.to.shared.u64 t, %1; cvt.u32.u64 %0, t; }" : "=r"(a) : "l"(p));
    return a;
}

__device__ __forceinline__ void cp_async16(uint32_t dst, const void* src){
    asm volatile("cp.async.cg.shared.global [%0], [%1], 16;" :: "r"(dst), "l"(src));
}
__device__ __forceinline__ void cp_commit(){ asm volatile("cp.async.commit_group;" ::: "memory"); }
template<int N> __device__ __forceinline__ void cp_wait(){ asm volatile("cp.async.wait_group %0;" :: "n"(N) : "memory"); }

__device__ __forceinline__ void ldm_x4(uint32_t addr, uint32_t& r0, uint32_t& r1, uint32_t& r2, uint32_t& r3){
    asm volatile("ldmatrix.sync.aligned.m8n8.x4.shared.b16 {%0,%1,%2,%3}, [%4];"
        : "=r"(r0), "=r"(r1), "=r"(r2), "=r"(r3) : "r"(addr));
}
__device__ __forceinline__ void mma16816(float& c0, float& c1, float& c2, float& c3,
                                         uint32_t a0, uint32_t a1, uint32_t a2, uint32_t a3,
                                         uint32_t b0, uint32_t b1){
    asm volatile("mma.sync.aligned.m16n8k16.row.col.f32.f16.f16.f32 "
        "{%0,%1,%2,%3}, {%4,%5,%6,%7}, {%8,%9}, {%0,%1,%2,%3};"
        : "+f"(c0), "+f"(c1), "+f"(c2), "+f"(c3)
        : "r"(a0), "r"(a1), "r"(a2), "r"(a3), "r"(b0), "r"(b1));
}

/* ---------------- split-fp16 conversion ---------------- */
__device__ __forceinline__ void splitH4(float4 v,
        __half2& hA, __half2& hB, __half2& lA, __half2& lB)
{
    __half h0=__float2half(v.x), h1=__float2half(v.y),
           h2=__float2half(v.z), h3=__float2half(v.w);
    lA.x=__float2half(v.x-__half2float(h0));
    lA.y=__float2half(v.y-__half2float(h1));
    lB.x=__float2half(v.z-__half2float(h2));
    lB.y=__float2half(v.w-__half2float(h3));
    hA.x=h0; hA.y=h1; hB.x=h2; hB.y=h3;
}

/* activations: [hi | lo] */
__global__ void split_act(const float* __restrict__ in, __half* __restrict__ out)
{
    long i = (long)blockIdx.x*256 + threadIdx.x;  /* over MTOT*192 float4 groups */
    if (i >= (long)MTOT*192) return;
    long r = i / 192; int c4 = (int)(i % 192);
    float4 v = *(const float4*)(in + r*768 + c4*4);
    __half2 hA,hB,lA,lB; splitH4(v,hA,hB,lA,lB);
    __half2* o0 = (__half2*)(out + r*KSPLIT + c4*4);
    __half2* o1 = (__half2*)(out + r*KSPLIT + 768 + c4*4);
    o0[0]=hA; o0[1]=hB;         /* hi */
    o1[0]=lA; o1[1]=lB;         /* lo */
}

/* weights: [hi | hi] (duplicated) -> product = A_full x W_hi */
struct WSplitJobs {
    const float* src[10];
    __half* dst[10];
    int nsrc[10];
    int npad[10];
};
__global__ void split_w_all(WSplitJobs J)
{
    int j = blockIdx.y;
    long i = (long)blockIdx.x*256 + threadIdx.x;
    int npad = J.npad[j];
    if (i >= (long)npad*192) return;
    int r = (int)(i / 192); int c4 = (int)(i % 192);
    float4 v = make_float4(0.f,0.f,0.f,0.f);
    if (r < J.nsrc[j]) v = *(const float4*)(J.src[j] + (long)r*768 + c4*4);
    __half2 hA,hB,lA,lB; splitH4(v,hA,hB,lA,lB);
    __half* out = J.dst[j];
    __half2* o0 = (__half2*)(out + (long)r*KSPLIT + c4*4);
    __half2* o1 = (__half2*)(out + (long)r*KSPLIT + 768 + c4*4);
    o0[0]=hA; o0[1]=hB;         /* hi */
    o1[0]=hA; o1[1]=hB;         /* hi */
}

/* ---------------- batched mma.sync GEMM ----------------
   per z-job: out[8192, Nout] = epi( sum_seg A_seg@B_seg^T + bias )
   CTA tile 128x128, BK=32, 8 warps (4m x 2n), warp tile 32x64.
   epi: 0 none, 1 tanh, 2 sigmoid(acc)*mult                       */
struct GemmJobs {
    const __half *A1[3], *B1[3], *A2[3], *B2[3];
    const float *bias[3], *mult[3];
    float *out[3];
    int nseg[3], Nout[3], ncol[3], epi[3];
};

__device__ __forceinline__ void load_stage(const __half* __restrict__ A,
                                           const __half* __restrict__ Bp,
                                           int kofs, uint32_t sbuf, int tid)
{
    uint32_t sA = sbuf, sB = sbuf + TILE_BYTES;
#pragma unroll
    for (int it = 0; it < 2; it++){        /* A: 128 rows x 4 chunks of 16B */
        int ci = it*256 + tid;
        int row = ci >> 2, c = ci & 3;
        cp_async16(sA + row*80 + c*16, A + (long)row*KSPLIT + kofs + c*8);
    }
#pragma unroll
    for (int it = 0; it < 2; it++){        /* B: 128 rows x 4 chunks */
        int ci = it*256 + tid;
        int row = ci >> 2, c = ci & 3;
        cp_async16(sB + row*80 + c*16, Bp + (long)row*KSPLIT + kofs + c*8);
    }
    cp_commit();
}

__global__ void __launch_bounds__(256, 2)
mma_gemm(GemmJobs J)
{
    extern __shared__ char dyn[];
    const int jz = blockIdx.z;
    if ((int)blockIdx.x >= J.ncol[jz]) return;
    const int tid  = threadIdx.x;
    const int lane = tid & 31;
    const int wid  = tid >> 5;
    const int wm   = wid & 3;        /* 0..3 : m */
    const int wn   = wid >> 2;       /* 0..1 : n */
    const int row0 = blockIdx.y * 128;
    const int col0 = blockIdx.x * 128;
    const int Nout = J.Nout[jz];
    const int epi  = J.epi[jz];
    const float* bias = J.bias[jz];
    const float* mult = J.mult[jz];
    float* out = J.out[jz];
    uint32_t sbase = (smem_u32(dyn) + 127u) & ~127u;

    const __half* Aseg[2];
    const __half* Bseg[2];
    Aseg[0] = J.A1[jz] + (long)row0*KSPLIT;
    Bseg[0] = J.B1[jz] + (long)col0*KSPLIT;
    Aseg[1] = J.A2[jz] ? (J.A2[jz] + (long)row0*KSPLIT) : Aseg[0];
    Bseg[1] = J.B2[jz] ? (J.B2[jz] + (long)col0*KSPLIT) : Bseg[0];
    const int SPS = KSPLIT / BKs;            /* 48 stages per segment */
    const int S = SPS * J.nseg[jz];

    float acc[2][8][4];
#pragma unroll
    for (int i=0;i<2;i++)
#pragma unroll
        for (int j=0;j<8;j++)
#pragma unroll
            for (int r=0;r<4;r++) acc[i][j][r]=0.f;

    int aM = lane & 15;
    int aK = (lane >> 4) * 8;
    int bN = ((lane >> 4) & 1)*8 + (lane & 7);
    int bK = ((lane >> 3) & 1)*8;

    /* prologue: stages 0..NSTG-2 */
#pragma unroll
    for (int p = 0; p < NSTG-1; p++)
        load_stage(Aseg[0], Bseg[0], p*BKs, sbase + p*STG_BYTES, tid);

    for (int s = 0; s < S; s++){
        cp_wait<NSTG-2>();
        __syncthreads();
        uint32_t sA = sbase + (s % NSTG)*STG_BYTES;
        uint32_t sB = sA + TILE_BYTES;
#pragma unroll
        for (int ks = 0; ks < 2; ks++){
            int k0 = ks*16;
            uint32_t a[2][4];
#pragma unroll
            for (int i=0;i<2;i++){
                uint32_t ad = sA + (uint32_t)(wm*32 + i*16 + aM)*80 + (uint32_t)(k0 + aK)*2;
                ldm_x4(ad, a[i][0], a[i][1], a[i][2], a[i][3]);
            }
            uint32_t b[8][2];
#pragma unroll
            for (int jj=0;jj<4;jj++){
                uint32_t bd = sB + (uint32_t)(wn*64 + jj*16 + bN)*80 + (uint32_t)(k0 + bK)*2;
                uint32_t r0,r1,r2,r3;
                ldm_x4(bd, r0, r1, r2, r3);
                b[2*jj][0]=r0; b[2*jj][1]=r1; b[2*jj+1][0]=r2; b[2*jj+1][1]=r3;
            }
#pragma unroll
            for (int i=0;i<2;i++)
#pragma unroll
                for (int j=0;j<8;j++)
                    mma16816(acc[i][j][0], acc[i][j][1], acc[i][j][2], acc[i][j][3],
                             a[i][0], a[i][1], a[i][2], a[i][3], b[j][0], b[j][1]);
        }
        int nl = s + NSTG - 1;
        if (nl < S){
            int seg = (nl >= SPS) ? 1 : 0;
            int ko  = (nl - seg*SPS) * BKs;
            load_stage(Aseg[seg], Bseg[seg], ko, sbase + (nl % NSTG)*STG_BYTES, tid);
        }
    }

    /* epilogue */
#pragma unroll
    for (int i=0;i<2;i++){
        int rlo = row0 + wm*32 + i*16 + (lane >> 2);
#pragma unroll
        for (int j=0;j<8;j++){
            int c = col0 + wn*64 + j*8 + (lane & 3)*2;
            if (c >= Nout) continue;
#pragma unroll
            for (int h=0;h<2;h++){
                long r = rlo + h*8;
                float v0 = acc[i][j][2*h], v1 = acc[i][j][2*h+1];
                if (bias){ v0 += bias[c]; v1 += bias[c+1]; }
                if (epi == 1){ v0 = tanhf(v0); v1 = tanhf(v1); }
                else if (epi == 2){
                    float m0 = mult[r*768 + c], m1 = mult[r*768 + c + 1];
                    v0 = m0 * sigmoidf_(v0); v1 = m1 * sigmoidf_(v1);
                }
                float2 st; st.x = v0; st.y = v1;
                *(float2*)(out + r*(long)Nout + c) = st;
            }
        }
    }
}

/* ---------------- SIMT GEMM (tiny anchor matmul) ---------------- */
__global__ void __launch_bounds__(256)
gemm_k(const float* __restrict__ A1, const float* __restrict__ W1, int K1,
       const float* __restrict__ bias,
       float* __restrict__ out, int M, int N, int epi)
{
    __shared__ float As[8][128];
    __shared__ float Bs[8][128];
    int tid  = threadIdx.x;
    int row0 = blockIdx.y * 128;
    int col0 = blockIdx.x * 128;
    int tx = tid & 15, ty = tid >> 4;
    float acc[8][8];
#pragma unroll
    for (int i=0;i<8;i++)
#pragma unroll
        for (int j=0;j<8;j++) acc[i][j]=0.f;

    int lr = tid >> 1;
    int lc = (tid & 1) * 4;

    for (int k0 = 0; k0 < K1; k0 += 8){
        float4 av = make_float4(0,0,0,0), wv = make_float4(0,0,0,0);
        int gr = row0 + lr;
        if (gr < M) av = *(const float4*)(A1 + (long)gr*K1 + k0 + lc);
        int gc = col0 + lr;
        if (gc < N) wv = *(const float4*)(W1 + (long)gc*K1 + k0 + lc);
        As[lc+0][lr]=av.x; As[lc+1][lr]=av.y; As[lc+2][lr]=av.z; As[lc+3][lr]=av.w;
        Bs[lc+0][lr]=wv.x; Bs[lc+1][lr]=wv.y; Bs[lc+2][lr]=wv.z; Bs[lc+3][lr]=wv.w;
        __syncthreads();
#pragma unroll
        for (int kk=0; kk<8; kk++){
            float4 a0 = *(const float4*)&As[kk][ty*8];
            float4 a1 = *(const float4*)&As[kk][ty*8+4];
            float4 b0 = *(const float4*)&Bs[kk][tx*8];
            float4 b1 = *(const float4*)&Bs[kk][tx*8+4];
            float ar[8]={a0.x,a0.y,a0.z,a0.w,a1.x,a1.y,a1.z,a1.w};
            float br[8]={b0.x,b0.y,b0.z,b0.w,b1.x,b1.y,b1.z,b1.w};
#pragma unroll
            for (int i=0;i<8;i++)
#pragma unroll
                for (int j=0;j<8;j++)
                    acc[i][j] += ar[i]*br[j];
        }
        __syncthreads();
    }
#pragma unroll
    for (int i=0;i<8;i++){
        int r = row0 + ty*8 + i;
        if (r >= M) continue;
#pragma unroll
        for (int j=0;j<8;j++){
            int c = col0 + tx*8 + j;
            if (c >= N) continue;
            float v = acc[i][j];
            if (bias) v += bias[c];
            if (epi == 1) v = tanhf(v);
            out[(long)r*N + c] = v;
        }
    }
}

/* ---------------- EMA: 3-phase chunked scan (z-batched jobs) ---------------- */
struct EP {
    const float* in;        /* p1 input */
    float* h;               /* p1 output / p3 input (chunk-local scan) */
    float* car;             /* carries */
    const float* tau;
    const float* cg;        /* optional */
    const float* delta;     /* optional */
    __half* outS;           /* p3 split output */
};
struct EPs { EP j[2]; };

__global__ void ema_p1(EPs E)
{
    const EP& e = E.j[blockIdx.z];
    int c  = blockIdx.y*256 + threadIdx.x;
    int b  = blockIdx.x / NCH, ch = blockIdx.x % NCH;
    float alpha = alpha_of(e.tau);
    const float* p  = e.in + ((long)b*Tt + ch*LCH)*Cc + c;
    float*       po = e.h  + ((long)b*Tt + ch*LCH)*Cc + c;
    float h = 0.f;
#pragma unroll 8
    for (int t=0; t<LCH; t++){
        h = alpha*h + p[(long)t*Cc];
        po[(long)t*Cc] = h;
    }
    e.car[((long)b*NCH + ch)*Cc + c] = h;
}

__global__ void ema_p2(EPs E)
{
    const EP& e = E.j[blockIdx.z];
    int i = blockIdx.x*256 + threadIdx.x;
    if (i >= Bb*Cc) return;
    int b = i / Cc, c = i % Cc;
    float alpha = alpha_of(e.tau);
    float aL = powf(alpha, (float)LCH);
    float H = 0.f;
    for (int ch=0; ch<NCH; ch++){
        float* pc = &e.car[((long)b*NCH+ch)*Cc + c];
        float cv = *pc;
        *pc = H;
        H = aL*H + cv;
    }
}

/* phase 3: inject carry, apply optional cg*+delta, emit split-fp16 [hi|lo] */
__global__ void ema_p3s(EPs E)
{
    const EP& e = E.j[blockIdx.z];
    int c  = blockIdx.y*256 + threadIdx.x;
    int b  = blockIdx.x / NCH, ch = blockIdx.x % NCH;
    float alpha = alpha_of(e.tau);
    float P = e.car[((long)b*NCH+ch)*Cc + c];
    const float* p = e.h + ((long)b*Tt + ch*LCH)*Cc + c;
    const float* cgp = e.cg ? (e.cg + (long)b*Tt + ch*LCH) : nullptr;
    float dl = e.delta ? e.delta[(long)b*Cc + c] : 0.f;
    __half* oS = e.outS + ((long)b*Tt + ch*LCH)*KSPLIT + c;
    float ap = alpha;
#pragma unroll 4
    for (int t=0; t<LCH; t++){
        float v = p[(long)t*Cc] + ap*P;
        if (cgp) v = v*cgp[t] + dl;
        __half h = __float2half(v);
        __half l = __float2half(v - __half2float(h));
        oS[(long)t*KSPLIT]       = h;
        oS[(long)t*KSPLIT + 768] = l;
        ap *= alpha;
    }
}

/* ---------------- causal max-score attention (q/k packed stride 256) ------- */
__global__ void __launch_bounds__(128)
attn_partmax(const float* __restrict__ qk, float* __restrict__ pm)
{
    const int nt = Tt / TTILE;
    int b  = blockIdx.x / nt, tt = blockIdx.x % nt;
    int sb = blockIdx.y;
    int t  = tt*TTILE + threadIdx.x;
    int tmax = tt*TTILE + TTILE - 1;
    int s_begin = sb * SBLEN;
    float m = -INFINITY;
    if (s_begin <= tmax){
        float qr[DKk];
        const float4* qp = (const float4*)(qk + ((long)b*Tt + t)*256);
#pragma unroll
        for (int i=0;i<DKk/4;i++){
            float4 v = qp[i];
            qr[4*i]=v.x; qr[4*i+1]=v.y; qr[4*i+2]=v.z; qr[4*i+3]=v.w;
        }
        __shared__ float ksh[64*DKk];
        int s_end = min(s_begin + SBLEN, tmax + 1);
        for (int s0 = s_begin; s0 < s_end; s0 += 64){
            __syncthreads();
            const float4* kp = (const float4*)(qk + (long)(b*Tt + s0)*256) + 32;
            float4* kd = (float4*)ksh;
            for (int i = threadIdx.x; i < 64*24; i += 128){
                int row = i / 24, cc = i % 24;
                kd[row*24 + cc] = kp[(long)row*64 + cc];
            }
            __syncthreads();
            int ssmax = min(64, t - s0 + 1);
            for (int ss=0; ss<ssmax; ss++){
                const float* kr = &ksh[ss*DKk];
                float a0=0.f,a1=0.f,a2=0.f,a3=0.f;
#pragma unroll
                for (int d=0; d<DKk; d+=16){
                    float4 k0 = *(const float4*)&kr[d];
                    float4 k1 = *(const float4*)&kr[d+4];
                    float4 k2 = *(const float4*)&kr[d+8];
                    float4 k3 = *(const float4*)&kr[d+12];
                    a0 += qr[d+0]*k0.x + qr[d+1]*k0.y + qr[d+2]*k0.z + qr[d+3]*k0.w;
                    a1 += qr[d+4]*k1.x + qr[d+5]*k1.y + qr[d+6]*k1.z + qr[d+7]*k1.w;
                    a2 += qr[d+8]*k2.x + qr[d+9]*k2.y + qr[d+10]*k2.z + qr[d+11]*k2.w;
                    a3 += qr[d+12]*k3.x + qr[d+13]*k3.y + qr[d+14]*k3.z + qr[d+15]*k3.w;
                }
                m = fmaxf(m, (a0+a1)+(a2+a3));
            }
        }
    }
    pm[((long)b*Tt + t)*NSB + sb] = m;
}

__global__ void attn_reduce(const float* __restrict__ pm, float* __restrict__ cgout)
{
    int i = blockIdx.x*256 + threadIdx.x;
    if (i >= MTOT) return;
    float m = pm[(long)i*NSB];
#pragma unroll
    for (int j=1;j<NSB;j++) m = fmaxf(m, pm[(long)i*NSB + j]);
    m *= rsqrtf((float)DKk);
    cgout[i] = sigmoidf_(m);
}

/* ---------------- anchors ---------------- */
__global__ void anchor_gather(const float* __restrict__ x, float* __restrict__ xa)
{
    int i = blockIdx.x*256 + threadIdx.x;
    if (i >= Bb*Nanc*Cc) return;
    int c = i % Cc;
    int n = (i / Cc) % Nanc;
    int b = i / (Cc*Nanc);
    int pos = n * (Tt / Nanc);
    if (pos > Tt-1) pos = Tt-1;
    xa[i] = x[((long)b*Tt + pos)*Cc + c];
}

__global__ void delta_k(const float* __restrict__ ancha, const float* __restrict__ scales,
                        float* __restrict__ delta)
{
    int i = blockIdx.x*256 + threadIdx.x;
    if (i >= Bb*Cc) return;
    int b = i / Cc, c = i % Cc;
    float s = 0.f;
#pragma unroll
    for (int n=0;n<Nanc;n++){
        float sg = sigmoidf_(scales[n]);
        s += sg * ancha[((long)b*Nanc + n)*Cc + c];
    }
    delta[i] = s;
}

/* ---------------- final gate + layernorm ---------------- */
__global__ void __launch_bounds__(256)
final_k(const float* __restrict__ gfr, const float* __restrict__ gsr,
        const float* __restrict__ somar, const float* __restrict__ blend,
        const float* __restrict__ lng, const float* __restrict__ lnb,
        float* __restrict__ out)
{
    long row = blockIdx.x;
    int tid = threadIdx.x;
    float bl = sigmoidf_(blend[0]);
    float y[3]; float s = 0.f, sq = 0.f;
#pragma unroll
    for (int j=0;j<3;j++){
        int c = tid + j*256;
        long idx = row*Cc + c;
        float f  = sigmoidf_(gfr[idx]);
        float g2 = sigmoidf_(gsr[idx]);
        float gate = f + bl*(g2 - f);
        float v = tanhf(somar[idx]) * gate;
        y[j] = v; s += v; sq += v*v;
    }
    __shared__ float rs[8], rq[8];
#pragma unroll
    for (int o=16;o>0;o>>=1){
        s  += __shfl_xor_sync(0xffffffffu, s,  o);
        sq += __shfl_xor_sync(0xffffffffu, sq, o);
    }
    if ((tid & 31) == 0){ rs[tid>>5] = s; rq[tid>>5] = sq; }
    __syncthreads();
    if (tid == 0){
        float ts=0.f, tq=0.f;
#pragma unroll
        for (int w=0;w<8;w++){ ts += rs[w]; tq += rq[w]; }
        rs[0] = ts; rq[0] = tq;
    }
    __syncthreads();
    float mu  = rs[0] / Cc;
    float var = rq[0] / Cc - mu*mu;
    float inv = rsqrtf(var + 1e-5f);
#pragma unroll
    for (int j=0;j<3;j++){
        int c = tid + j*256;
        long idx = row*Cc + c;
        out[idx] = (y[j]-mu)*inv*lng[c] + lnb[c];
    }
}

/* ---------------- launch ---------------- */
static float* symaddr(const void* sym){
    void* p = nullptr;
    cudaGetSymbolAddress(&p, sym);
    return (float*)p;
}
static __half* symaddrh(const void* sym){
    void* p = nullptr;
    cudaGetSymbolAddress(&p, sym);
    return (__half*)p;
}

extern "C" void kernel_launch(void* const* d_in, const int* in_sizes, int n_in,
                              void* d_out, int out_size)
{
    const float* x        = (const float*)d_in[0];
    const float* tau_gate = (const float*)d_in[1];
    const float* tau_fast = (const float*)d_in[2];
    const float* tau_slow = (const float*)d_in[3];
    const float* Wp   = (const float*)d_in[4];
    const float* bp   = (const float*)d_in[5];
    const float* Wxf  = (const float*)d_in[6];
    const float* bxf  = (const float*)d_in[7];
    const float* Wxs  = (const float*)d_in[8];
    const float* bxs  = (const float*)d_in[9];
    const float* Wcf  = (const float*)d_in[10];
    const float* Wcs  = (const float*)d_in[11];
    const float* Wq   = (const float*)d_in[12];
    const float* Wk   = (const float*)d_in[13];
    const float* Wfast= (const float*)d_in[14];
    const float* bfast= (const float*)d_in[15];
    const float* Wslow= (const float*)d_in[16];
    const float* bslow= (const float*)d_in[17];
    const float* Wsoma= (const float*)d_in[18];
    const float* bsoma= (const float*)d_in[19];
    const float* Wanc = (const float*)d_in[20];
    const float* banc = (const float*)d_in[21];
    const float* ascl = (const float*)d_in[22];
    const float* blend= (const float*)d_in[23];
    const float* lng  = (const float*)d_in[24];
    const float* lnb  = (const float*)d_in[25];
    float* out = (float*)d_out;

    float* xproj = symaddr(d_xproj);
    float* ctxg  = symaddr(d_ctxg);
    float* bfp   = symaddr(d_bf);
    float* bsp   = symaddr(d_bs);
    float* cfp   = symaddr(d_cf);
    float* csp   = symaddr(d_cs);
    float* gfr   = symaddr(d_gfr);
    float* gsr   = symaddr(d_gsr);
    float* somar = symaddr(d_somar);
    float* qk    = symaddr(d_qk);
    float* pm    = symaddr(d_pm);
    float* cg    = symaddr(d_cg);
    float* xa    = symaddr(d_xa);
    float* ancha = symaddr(d_ancha);
    float* delta = symaddr(d_delta);
    float* carG  = symaddr(d_carG);
    float* carF  = symaddr(d_carF);
    float* carS  = symaddr(d_carS);

    __half* xS    = symaddrh(d_xS);
    __half* ctxgS = symaddrh(d_ctxgS);
    __half* cfS   = symaddrh(d_cfS);
    __half* csS   = symaddrh(d_csS);
    __half* WpS   = symaddrh(d_WpS);
    __half* WxfS  = symaddrh(d_WxfS);
    __half* WxsS  = symaddrh(d_WxsS);
    __half* WcfS  = symaddrh(d_WcfS);
    __half* WcsS  = symaddrh(d_WcsS);
    __half* WfastS= symaddrh(d_WfastS);
    __half* WslowS= symaddrh(d_WslowS);
    __half* WsomaS= symaddrh(d_WsomaS);
    __half* WqkS  = symaddrh(d_WqkS);

    cudaFuncSetAttribute(mma_gemm, cudaFuncAttributeMaxDynamicSharedMemorySize, SMEMSZ);

    dim3 gema(Bb*NCH, Cc/256, 1);
    dim3 gema2(Bb*NCH, Cc/256, 2);

    /* 1: x split */
    split_act<<<(MTOT*192+255)/256, 256>>>(x, xS);

    /* 2: all weight splits in one launch */
    {
        WSplitJobs WJ;
        const float* srcs[10] = {Wp,Wxf,Wxs,Wcf,Wcs,Wfast,Wslow,Wsoma,Wq,Wk};
        __half* dsts[10] = {WpS,WxfS,WxsS,WcfS,WcsS,WfastS,WslowS,WsomaS,
                            WqkS, WqkS + (long)128*KSPLIT};
        int ns[10] = {768,768,768,768,768,768,768,768,DKk,DKk};
        int np[10] = {768,768,768,768,768,768,768,768,128,128};
        for (int i=0;i<10;i++){ WJ.src[i]=srcs[i]; WJ.dst[i]=dsts[i]; WJ.nsrc[i]=ns[i]; WJ.npad[i]=np[i]; }
        split_w_all<<<dim3(576,10), 256>>>(WJ);
    }

    /* 3: ctx_gate EMA on x -> ctxgS */
    {
        EPs E; E.j[0] = {x, ctxg, carG, tau_gate, nullptr, nullptr, ctxgS}; E.j[1] = E.j[0];
        ema_p1<<<gema, 256>>>(E);
        ema_p2<<<dim3((Bb*Cc+255)/256,1,1), 256>>>(E);
        ema_p3s<<<gema, 256>>>(E);
    }

    /* 4: batch1 gemm: xproj (tanh) + qk */
    {
        GemmJobs G = {};
        G.A1[0]=xS;  G.B1[0]=WpS;  G.nseg[0]=1; G.bias[0]=bp;     G.out[0]=xproj; G.Nout[0]=768; G.ncol[0]=6; G.epi[0]=1;
        G.A1[1]=xS;  G.B1[1]=WqkS; G.nseg[1]=1; G.bias[1]=nullptr;G.out[1]=qk;    G.Nout[1]=256; G.ncol[1]=2; G.epi[1]=0;
        mma_gemm<<<dim3(6, MTOT/128, 2), 256, SMEMSZ>>>(G);
    }

    /* 5: content gate cg */
    attn_partmax<<<dim3(Bb*(Tt/TTILE), NSB), 128>>>(qk, pm);
    attn_reduce<<<(MTOT+255)/256, 256>>>(pm, cg);

    /* 6: anchors -> delta (tiny, SIMT) */
    anchor_gather<<<(Bb*Nanc*Cc+255)/256, 256>>>(x, xa);
    gemm_k<<<dim3(Cc/128,1), 256>>>(xa, Wanc, Cc, banc, ancha, Bb*Nanc, Cc, 1);
    delta_k<<<(Bb*Cc+255)/256, 256>>>(ancha, ascl, delta);

    /* 7: batch2 gemm: bf, bs (sigmoid * xproj) */
    {
        GemmJobs G = {};
        G.A1[0]=xS; G.B1[0]=WxfS; G.A2[0]=ctxgS; G.B2[0]=WcfS; G.nseg[0]=2;
        G.bias[0]=bxf; G.mult[0]=xproj; G.out[0]=bfp; G.Nout[0]=768; G.ncol[0]=6; G.epi[0]=2;
        G.A1[1]=xS; G.B1[1]=WxsS; G.A2[1]=ctxgS; G.B2[1]=WcsS; G.nseg[1]=2;
        G.bias[1]=bxs; G.mult[1]=xproj; G.out[1]=bsp; G.Nout[1]=768; G.ncol[1]=6; G.epi[1]=2;
        mma_gemm<<<dim3(6, MTOT/128, 2), 256, SMEMSZ>>>(G);
    }

    /* 8: fast/slow EMAs (z-batched), phase3 fuses *cg + delta and split output */
    {
        EPs E;
        E.j[0] = {bfp, cfp, carF, tau_fast, cg, delta, cfS};
        E.j[1] = {bsp, csp, carS, tau_slow, cg, delta, csS};
        ema_p1<<<gema2, 256>>>(E);
        ema_p2<<<dim3((Bb*Cc+255)/256,1,2), 256>>>(E);
        ema_p3s<<<gema2, 256>>>(E);
    }

    /* 9: batch3 gemm: gfr, gsr, somar */
    {
        GemmJobs G = {};
        G.A1[0]=cfS; G.B1[0]=WfastS; G.nseg[0]=1; G.bias[0]=bfast; G.out[0]=gfr;   G.Nout[0]=768; G.ncol[0]=6; G.epi[0]=0;
        G.A1[1]=csS; G.B1[1]=WslowS; G.nseg[1]=1; G.bias[1]=bslow; G.out[1]=gsr;   G.Nout[1]=768; G.ncol[1]=6; G.epi[1]=0;
        G.A1[2]=xS;  G.B1[2]=WsomaS; G.nseg[2]=1; G.bias[2]=bsoma; G.out[2]=somar; G.Nout[2]=768; G.ncol[2]=6; G.epi[2]=0;
        mma_gemm<<<dim3(6, MTOT/128, 3), 256, SMEMSZ>>>(G);
    }

    /* 10: fused gates + layernorm */
    final_k<<<MTOT, 256>>>(gfr, gsr, somar, blend, lng, lnb, out);
}

// round 6
// speedup vs baseline: 4.5712x; 1.3458x over previous
#include <cuda_runtime.h>
#include <cuda_fp16.h>
#include <cstdint>
#include <math.h>

#define Bb 4
#define Tt 2048
#define Cc 768
#define DKk 96
#define Nanc 8
#define NCH 32
#define LCH 64          /* Tt / NCH */
#define NSB 8
#define SBLEN 256
#define TTILE 128
#define MTOT (Bb*Tt)    /* 8192 */

#define KA 768          /* fp16 K (no split expansion) */
#define BKs 32          /* K per stage */
#define TILE_BYTES (128*40*2)           /* 10240 (row stride 80B) */
#define STG_BYTES (2*TILE_BYTES)        /* A+B per stage: 20480 */
#define NSTG 3
#define SMEMSZ (NSTG*STG_BYTES + 256)   /* 61696 -> 2 CTAs/SM */

/* ------------ device scratch (static, no allocation) ------------- */
__device__ float d_xproj[MTOT*Cc];
__device__ float d_ctxg [MTOT*Cc];
__device__ float d_bf   [MTOT*Cc];
__device__ float d_bs   [MTOT*Cc];
__device__ float d_cf   [MTOT*Cc];
__device__ float d_cs   [MTOT*Cc];
__device__ float d_gfr  [MTOT*Cc];
__device__ float d_gsr  [MTOT*Cc];
__device__ float d_somar[MTOT*Cc];
__device__ float d_qk   [MTOT*256];
__device__ float d_pm   [MTOT*NSB];
__device__ float d_cg   [MTOT];
__device__ float d_xa   [Bb*Nanc*Cc];
__device__ float d_ancha[Bb*Nanc*Cc];
__device__ float d_delta[Bb*Cc];
__device__ float d_carG [Bb*NCH*Cc];
__device__ float d_carF [Bb*NCH*Cc];
__device__ float d_carS [Bb*NCH*Cc];

/* fp16 buffers */
__device__ __half d_xH   [(long)MTOT*KA];
__device__ __half d_ctxgH[(long)MTOT*KA];
__device__ __half d_cfH  [(long)MTOT*KA];
__device__ __half d_csH  [(long)MTOT*KA];
__device__ __half d_WpH   [768*KA];
__device__ __half d_WxfH  [768*KA];
__device__ __half d_WxsH  [768*KA];
__device__ __half d_WcfH  [768*KA];
__device__ __half d_WcsH  [768*KA];
__device__ __half d_WfastH[768*KA];
__device__ __half d_WslowH[768*KA];
__device__ __half d_WsomaH[768*KA];
__device__ __half d_WqkH  [256*KA];

/* ---------------- helpers ---------------- */
__device__ __forceinline__ float alpha_of(const float* tau){
    float t = *tau;
    float sp = (t > 20.f) ? t : log1pf(expf(t));
    return expf(-sp);
}
__device__ __forceinline__ float sigmoidf_(float v){ return 1.f/(1.f+expf(-v)); }

__device__ __forceinline__ uint32_t smem_u32(const void* p){
    uint32_t a;
    asm("{ .reg .u64 t; cvta.to.shared.u64 t, %1; cvt.u32.u64 %0, t; }" : "=r"(a) : "l"(p));
    return a;
}

__device__ __forceinline__ void cp_async16(uint32_t dst, const void* src){
    asm volatile("cp.async.cg.shared.global [%0], [%1], 16;" :: "r"(dst), "l"(src));
}
__device__ __forceinline__ void cp_commit(){ asm volatile("cp.async.commit_group;" ::: "memory"); }
template<int N> __device__ __forceinline__ void cp_wait(){ asm volatile("cp.async.wait_group %0;" :: "n"(N) : "memory"); }

__device__ __forceinline__ void ldm_x4(uint32_t addr, uint32_t& r0, uint32_t& r1, uint32_t& r2, uint32_t& r3){
    asm volatile("ldmatrix.sync.aligned.m8n8.x4.shared.b16 {%0,%1,%2,%3}, [%4];"
        : "=r"(r0), "=r"(r1), "=r"(r2), "=r"(r3) : "r"(addr));
}
__device__ __forceinline__ void mma16816(float& c0, float& c1, float& c2, float& c3,
                                         uint32_t a0, uint32_t a1, uint32_t a2, uint32_t a3,
                                         uint32_t b0, uint32_t b1){
    asm volatile("mma.sync.aligned.m16n8k16.row.col.f32.f16.f16.f32 "
        "{%0,%1,%2,%3}, {%4,%5,%6,%7}, {%8,%9}, {%0,%1,%2,%3};"
        : "+f"(c0), "+f"(c1), "+f"(c2), "+f"(c3)
        : "r"(a0), "r"(a1), "r"(a2), "r"(a3), "r"(b0), "r"(b1));
}

/* ---------------- fp16 conversion kernels ---------------- */
__global__ void conv_act(const float* __restrict__ in, __half* __restrict__ out)
{
    long i = (long)blockIdx.x*256 + threadIdx.x;  /* over MTOT*192 float4 groups */
    if (i >= (long)MTOT*192) return;
    float4 v = *(const float4*)(in + i*4);
    __half2 a; a.x=__float2half(v.x); a.y=__float2half(v.y);
    __half2 b; b.x=__float2half(v.z); b.y=__float2half(v.w);
    __half2* o = (__half2*)(out + i*4);
    o[0]=a; o[1]=b;
}

struct WConvJobs {
    const float* src[10];
    __half* dst[10];
    int nsrc[10];
    int npad[10];
};
__global__ void conv_w_all(WConvJobs J)
{
    int j = blockIdx.y;
    long i = (long)blockIdx.x*256 + threadIdx.x;
    int npad = J.npad[j];
    if (i >= (long)npad*192) return;
    int r = (int)(i / 192); int c4 = (int)(i % 192);
    float4 v = make_float4(0.f,0.f,0.f,0.f);
    if (r < J.nsrc[j]) v = *(const float4*)(J.src[j] + (long)r*768 + c4*4);
    __half2 a; a.x=__float2half(v.x); a.y=__float2half(v.y);
    __half2 b; b.x=__float2half(v.z); b.y=__float2half(v.w);
    __half2* o = (__half2*)(J.dst[j] + (long)r*KA + c4*4);
    o[0]=a; o[1]=b;
}

/* ---------------- batched mma.sync GEMM ----------------
   per z-job: out[8192, Nout] = epi( sum_seg A_seg@B_seg^T + bias )
   CTA tile 128x128, BK=32, 8 warps (4m x 2n), warp tile 32x64.
   epi: 0 none, 1 tanh, 2 sigmoid(acc)*mult                       */
struct GemmJobs {
    const __half *A1[3], *B1[3], *A2[3], *B2[3];
    const float *bias[3], *mult[3];
    float *out[3];
    int nseg[3], Nout[3], ncol[3], epi[3];
};

__device__ __forceinline__ void load_stage(const __half* __restrict__ A,
                                           const __half* __restrict__ Bp,
                                           int kofs, uint32_t sbuf, int tid)
{
    uint32_t sA = sbuf, sB = sbuf + TILE_BYTES;
#pragma unroll
    for (int it = 0; it < 2; it++){        /* A: 128 rows x 4 chunks of 16B */
        int ci = it*256 + tid;
        int row = ci >> 2, c = ci & 3;
        cp_async16(sA + row*80 + c*16, A + (long)row*KA + kofs + c*8);
    }
#pragma unroll
    for (int it = 0; it < 2; it++){        /* B: 128 rows x 4 chunks */
        int ci = it*256 + tid;
        int row = ci >> 2, c = ci & 3;
        cp_async16(sB + row*80 + c*16, Bp + (long)row*KA + kofs + c*8);
    }
    cp_commit();
}

__global__ void __launch_bounds__(256, 2)
mma_gemm(GemmJobs J)
{
    extern __shared__ char dyn[];
    const int jz = blockIdx.z;
    if ((int)blockIdx.x >= J.ncol[jz]) return;
    const int tid  = threadIdx.x;
    const int lane = tid & 31;
    const int wid  = tid >> 5;
    const int wm   = wid & 3;        /* 0..3 : m */
    const int wn   = wid >> 2;       /* 0..1 : n */
    const int row0 = blockIdx.y * 128;
    const int col0 = blockIdx.x * 128;
    const int Nout = J.Nout[jz];
    const int epi  = J.epi[jz];
    const float* bias = J.bias[jz];
    const float* mult = J.mult[jz];
    float* out = J.out[jz];
    uint32_t sbase = (smem_u32(dyn) + 127u) & ~127u;

    const __half* Aseg[2];
    const __half* Bseg[2];
    Aseg[0] = J.A1[jz] + (long)row0*KA;
    Bseg[0] = J.B1[jz] + (long)col0*KA;
    Aseg[1] = J.A2[jz] ? (J.A2[jz] + (long)row0*KA) : Aseg[0];
    Bseg[1] = J.B2[jz] ? (J.B2[jz] + (long)col0*KA) : Bseg[0];
    const int SPS = KA / BKs;            /* 24 stages per segment */
    const int S = SPS * J.nseg[jz];

    float acc[2][8][4];
#pragma unroll
    for (int i=0;i<2;i++)
#pragma unroll
        for (int j=0;j<8;j++)
#pragma unroll
            for (int r=0;r<4;r++) acc[i][j][r]=0.f;

    int aM = lane & 15;
    int aK = (lane >> 4) * 8;
    int bN = ((lane >> 4) & 1)*8 + (lane & 7);
    int bK = ((lane >> 3) & 1)*8;

    /* prologue: stages 0..NSTG-2 */
#pragma unroll
    for (int p = 0; p < NSTG-1; p++)
        load_stage(Aseg[0], Bseg[0], p*BKs, sbase + p*STG_BYTES, tid);

    for (int s = 0; s < S; s++){
        cp_wait<NSTG-2>();
        __syncthreads();
        uint32_t sA = sbase + (s % NSTG)*STG_BYTES;
        uint32_t sB = sA + TILE_BYTES;
#pragma unroll
        for (int ks = 0; ks < 2; ks++){
            int k0 = ks*16;
            uint32_t a[2][4];
#pragma unroll
            for (int i=0;i<2;i++){
                uint32_t ad = sA + (uint32_t)(wm*32 + i*16 + aM)*80 + (uint32_t)(k0 + aK)*2;
                ldm_x4(ad, a[i][0], a[i][1], a[i][2], a[i][3]);
            }
            uint32_t b[8][2];
#pragma unroll
            for (int jj=0;jj<4;jj++){
                uint32_t bd = sB + (uint32_t)(wn*64 + jj*16 + bN)*80 + (uint32_t)(k0 + bK)*2;
                uint32_t r0,r1,r2,r3;
                ldm_x4(bd, r0, r1, r2, r3);
                b[2*jj][0]=r0; b[2*jj][1]=r1; b[2*jj+1][0]=r2; b[2*jj+1][1]=r3;
            }
#pragma unroll
            for (int i=0;i<2;i++)
#pragma unroll
                for (int j=0;j<8;j++)
                    mma16816(acc[i][j][0], acc[i][j][1], acc[i][j][2], acc[i][j][3],
                             a[i][0], a[i][1], a[i][2], a[i][3], b[j][0], b[j][1]);
        }
        int nl = s + NSTG - 1;
        if (nl < S){
            int seg = (nl >= SPS) ? 1 : 0;
            int ko  = (nl - seg*SPS) * BKs;
            load_stage(Aseg[seg], Bseg[seg], ko, sbase + (nl % NSTG)*STG_BYTES, tid);
        }
    }

    /* epilogue */
#pragma unroll
    for (int i=0;i<2;i++){
        int rlo = row0 + wm*32 + i*16 + (lane >> 2);
#pragma unroll
        for (int j=0;j<8;j++){
            int c = col0 + wn*64 + j*8 + (lane & 3)*2;
            if (c >= Nout) continue;
#pragma unroll
            for (int h=0;h<2;h++){
                long r = rlo + h*8;
                float v0 = acc[i][j][2*h], v1 = acc[i][j][2*h+1];
                if (bias){ v0 += bias[c]; v1 += bias[c+1]; }
                if (epi == 1){ v0 = tanhf(v0); v1 = tanhf(v1); }
                else if (epi == 2){
                    float m0 = mult[r*768 + c], m1 = mult[r*768 + c + 1];
                    v0 = m0 * sigmoidf_(v0); v1 = m1 * sigmoidf_(v1);
                }
                float2 st; st.x = v0; st.y = v1;
                *(float2*)(out + r*(long)Nout + c) = st;
            }
        }
    }
}

/* ---------------- SIMT GEMM (tiny anchor matmul) ---------------- */
__global__ void __launch_bounds__(256)
gemm_k(const float* __restrict__ A1, const float* __restrict__ W1, int K1,
       const float* __restrict__ bias,
       float* __restrict__ out, int M, int N, int epi)
{
    __shared__ float As[8][128];
    __shared__ float Bs[8][128];
    int tid  = threadIdx.x;
    int row0 = blockIdx.y * 128;
    int col0 = blockIdx.x * 128;
    int tx = tid & 15, ty = tid >> 4;
    float acc[8][8];
#pragma unroll
    for (int i=0;i<8;i++)
#pragma unroll
        for (int j=0;j<8;j++) acc[i][j]=0.f;

    int lr = tid >> 1;
    int lc = (tid & 1) * 4;

    for (int k0 = 0; k0 < K1; k0 += 8){
        float4 av = make_float4(0,0,0,0), wv = make_float4(0,0,0,0);
        int gr = row0 + lr;
        if (gr < M) av = *(const float4*)(A1 + (long)gr*K1 + k0 + lc);
        int gc = col0 + lr;
        if (gc < N) wv = *(const float4*)(W1 + (long)gc*K1 + k0 + lc);
        As[lc+0][lr]=av.x; As[lc+1][lr]=av.y; As[lc+2][lr]=av.z; As[lc+3][lr]=av.w;
        Bs[lc+0][lr]=wv.x; Bs[lc+1][lr]=wv.y; Bs[lc+2][lr]=wv.z; Bs[lc+3][lr]=wv.w;
        __syncthreads();
#pragma unroll
        for (int kk=0; kk<8; kk++){
            float4 a0 = *(const float4*)&As[kk][ty*8];
            float4 a1 = *(const float4*)&As[kk][ty*8+4];
            float4 b0 = *(const float4*)&Bs[kk][tx*8];
            float4 b1 = *(const float4*)&Bs[kk][tx*8+4];
            float ar[8]={a0.x,a0.y,a0.z,a0.w,a1.x,a1.y,a1.z,a1.w};
            float br[8]={b0.x,b0.y,b0.z,b0.w,b1.x,b1.y,b1.z,b1.w};
#pragma unroll
            for (int i=0;i<8;i++)
#pragma unroll
                for (int j=0;j<8;j++)
                    acc[i][j] += ar[i]*br[j];
        }
        __syncthreads();
    }
#pragma unroll
    for (int i=0;i<8;i++){
        int r = row0 + ty*8 + i;
        if (r >= M) continue;
#pragma unroll
        for (int j=0;j<8;j++){
            int c = col0 + tx*8 + j;
            if (c >= N) continue;
            float v = acc[i][j];
            if (bias) v += bias[c];
            if (epi == 1) v = tanhf(v);
            out[(long)r*N + c] = v;
        }
    }
}

/* ---------------- EMA: 3-phase chunked scan (z-batched jobs) ---------------- */
struct EP {
    const float* in;        /* p1 input */
    float* h;               /* p1 output / p3 input (chunk-local scan) */
    float* car;             /* carries */
    const float* tau;
    const float* cg;        /* optional */
    const float* delta;     /* optional */
    __half* outH;           /* p3 fp16 output */
};
struct EPs { EP j[2]; };

__global__ void ema_p1(EPs E)
{
    const EP& e = E.j[blockIdx.z];
    int c  = blockIdx.y*256 + threadIdx.x;
    int b  = blockIdx.x / NCH, ch = blockIdx.x % NCH;
    float alpha = alpha_of(e.tau);
    const float* p  = e.in + ((long)b*Tt + ch*LCH)*Cc + c;
    float*       po = e.h  + ((long)b*Tt + ch*LCH)*Cc + c;
    float h = 0.f;
#pragma unroll 8
    for (int t=0; t<LCH; t++){
        h = alpha*h + p[(long)t*Cc];
        po[(long)t*Cc] = h;
    }
    e.car[((long)b*NCH + ch)*Cc + c] = h;
}

__global__ void ema_p2(EPs E)
{
    const EP& e = E.j[blockIdx.z];
    int i = blockIdx.x*256 + threadIdx.x;
    if (i >= Bb*Cc) return;
    int b = i / Cc, c = i % Cc;
    float alpha = alpha_of(e.tau);
    float aL = powf(alpha, (float)LCH);
    float H = 0.f;
    for (int ch=0; ch<NCH; ch++){
        float* pc = &e.car[((long)b*NCH+ch)*Cc + c];
        float cv = *pc;
        *pc = H;
        H = aL*H + cv;
    }
}

/* phase 3: inject carry, apply optional cg*+delta, emit fp16 */
__global__ void ema_p3s(EPs E)
{
    const EP& e = E.j[blockIdx.z];
    int c  = blockIdx.y*256 + threadIdx.x;
    int b  = blockIdx.x / NCH, ch = blockIdx.x % NCH;
    float alpha = alpha_of(e.tau);
    float P = e.car[((long)b*NCH+ch)*Cc + c];
    const float* p = e.h + ((long)b*Tt + ch*LCH)*Cc + c;
    const float* cgp = e.cg ? (e.cg + (long)b*Tt + ch*LCH) : nullptr;
    float dl = e.delta ? e.delta[(long)b*Cc + c] : 0.f;
    __half* oH = e.outH + ((long)b*Tt + ch*LCH)*KA + c;
    float ap = alpha;
#pragma unroll 4
    for (int t=0; t<LCH; t++){
        float v = p[(long)t*Cc] + ap*P;
        if (cgp) v = v*cgp[t] + dl;
        oH[(long)t*KA] = __float2half(v);
        ap *= alpha;
    }
}

/* ---------------- causal max-score attention (q/k packed stride 256) ------- */
__global__ void __launch_bounds__(128)
attn_partmax(const float* __restrict__ qk, float* __restrict__ pm)
{
    const int nt = Tt / TTILE;
    int b  = blockIdx.x / nt, tt = blockIdx.x % nt;
    int sb = blockIdx.y;
    int t  = tt*TTILE + threadIdx.x;
    int tmax = tt*TTILE + TTILE - 1;
    int s_begin = sb * SBLEN;
    float m = -INFINITY;
    if (s_begin <= tmax){
        float qr[DKk];
        const float4* qp = (const float4*)(qk + ((long)b*Tt + t)*256);
#pragma unroll
        for (int i=0;i<DKk/4;i++){
            float4 v = qp[i];
            qr[4*i]=v.x; qr[4*i+1]=v.y; qr[4*i+2]=v.z; qr[4*i+3]=v.w;
        }
        __shared__ float ksh[64*DKk];
        int s_end = min(s_begin + SBLEN, tmax + 1);
        for (int s0 = s_begin; s0 < s_end; s0 += 64){
            __syncthreads();
            const float4* kp = (const float4*)(qk + (long)(b*Tt + s0)*256) + 32;
            float4* kd = (float4*)ksh;
            for (int i = threadIdx.x; i < 64*24; i += 128){
                int row = i / 24, cc = i % 24;
                kd[row*24 + cc] = kp[(long)row*64 + cc];
            }
            __syncthreads();
            int ssmax = min(64, t - s0 + 1);
            for (int ss=0; ss<ssmax; ss++){
                const float* kr = &ksh[ss*DKk];
                float a0=0.f,a1=0.f,a2=0.f,a3=0.f;
#pragma unroll
                for (int d=0; d<DKk; d+=16){
                    float4 k0 = *(const float4*)&kr[d];
                    float4 k1 = *(const float4*)&kr[d+4];
                    float4 k2 = *(const float4*)&kr[d+8];
                    float4 k3 = *(const float4*)&kr[d+12];
                    a0 += qr[d+0]*k0.x + qr[d+1]*k0.y + qr[d+2]*k0.z + qr[d+3]*k0.w;
                    a1 += qr[d+4]*k1.x + qr[d+5]*k1.y + qr[d+6]*k1.z + qr[d+7]*k1.w;
                    a2 += qr[d+8]*k2.x + qr[d+9]*k2.y + qr[d+10]*k2.z + qr[d+11]*k2.w;
                    a3 += qr[d+12]*k3.x + qr[d+13]*k3.y + qr[d+14]*k3.z + qr[d+15]*k3.w;
                }
                m = fmaxf(m, (a0+a1)+(a2+a3));
            }
        }
    }
    pm[((long)b*Tt + t)*NSB + sb] = m;
}

__global__ void attn_reduce(const float* __restrict__ pm, float* __restrict__ cgout)
{
    int i = blockIdx.x*256 + threadIdx.x;
    if (i >= MTOT) return;
    float m = pm[(long)i*NSB];
#pragma unroll
    for (int j=1;j<NSB;j++) m = fmaxf(m, pm[(long)i*NSB + j]);
    m *= rsqrtf((float)DKk);
    cgout[i] = sigmoidf_(m);
}

/* ---------------- anchors ---------------- */
__global__ void anchor_gather(const float* __restrict__ x, float* __restrict__ xa)
{
    int i = blockIdx.x*256 + threadIdx.x;
    if (i >= Bb*Nanc*Cc) return;
    int c = i % Cc;
    int n = (i / Cc) % Nanc;
    int b = i / (Cc*Nanc);
    int pos = n * (Tt / Nanc);
    if (pos > Tt-1) pos = Tt-1;
    xa[i] = x[((long)b*Tt + pos)*Cc + c];
}

__global__ void delta_k(const float* __restrict__ ancha, const float* __restrict__ scales,
                        float* __restrict__ delta)
{
    int i = blockIdx.x*256 + threadIdx.x;
    if (i >= Bb*Cc) return;
    int b = i / Cc, c = i % Cc;
    float s = 0.f;
#pragma unroll
    for (int n=0;n<Nanc;n++){
        float sg = sigmoidf_(scales[n]);
        s += sg * ancha[((long)b*Nanc + n)*Cc + c];
    }
    delta[i] = s;
}

/* ---------------- final gate + layernorm ---------------- */
__global__ void __launch_bounds__(256)
final_k(const float* __restrict__ gfr, const float* __restrict__ gsr,
        const float* __restrict__ somar, const float* __restrict__ blend,
        const float* __restrict__ lng, const float* __restrict__ lnb,
        float* __restrict__ out)
{
    long row = blockIdx.x;
    int tid = threadIdx.x;
    float bl = sigmoidf_(blend[0]);
    float y[3]; float s = 0.f, sq = 0.f;
#pragma unroll
    for (int j=0;j<3;j++){
        int c = tid + j*256;
        long idx = row*Cc + c;
        float f  = sigmoidf_(gfr[idx]);
        float g2 = sigmoidf_(gsr[idx]);
        float gate = f + bl*(g2 - f);
        float v = tanhf(somar[idx]) * gate;
        y[j] = v; s += v; sq += v*v;
    }
    __shared__ float rs[8], rq[8];
#pragma unroll
    for (int o=16;o>0;o>>=1){
        s  += __shfl_xor_sync(0xffffffffu, s,  o);
        sq += __shfl_xor_sync(0xffffffffu, sq, o);
    }
    if ((tid & 31) == 0){ rs[tid>>5] = s; rq[tid>>5] = sq; }
    __syncthreads();
    if (tid == 0){
        float ts=0.f, tq=0.f;
#pragma unroll
        for (int w=0;w<8;w++){ ts += rs[w]; tq += rq[w]; }
        rs[0] = ts; rq[0] = tq;
    }
    __syncthreads();
    float mu  = rs[0] / Cc;
    float var = rq[0] / Cc - mu*mu;
    float inv = rsqrtf(var + 1e-5f);
#pragma unroll
    for (int j=0;j<3;j++){
        int c = tid + j*256;
        long idx = row*Cc + c;
        out[idx] = (y[j]-mu)*inv*lng[c] + lnb[c];
    }
}

/* ---------------- launch ---------------- */
static float* symaddr(const void* sym){
    void* p = nullptr;
    cudaGetSymbolAddress(&p, sym);
    return (float*)p;
}
static __half* symaddrh(const void* sym){
    void* p = nullptr;
    cudaGetSymbolAddress(&p, sym);
    return (__half*)p;
}

extern "C" void kernel_launch(void* const* d_in, const int* in_sizes, int n_in,
                              void* d_out, int out_size)
{
    const float* x        = (const float*)d_in[0];
    const float* tau_gate = (const float*)d_in[1];
    const float* tau_fast = (const float*)d_in[2];
    const float* tau_slow = (const float*)d_in[3];
    const float* Wp   = (const float*)d_in[4];
    const float* bp   = (const float*)d_in[5];
    const float* Wxf  = (const float*)d_in[6];
    const float* bxf  = (const float*)d_in[7];
    const float* Wxs  = (const float*)d_in[8];
    const float* bxs  = (const float*)d_in[9];
    const float* Wcf  = (const float*)d_in[10];
    const float* Wcs  = (const float*)d_in[11];
    const float* Wq   = (const float*)d_in[12];
    const float* Wk   = (const float*)d_in[13];
    const float* Wfast= (const float*)d_in[14];
    const float* bfast= (const float*)d_in[15];
    const float* Wslow= (const float*)d_in[16];
    const float* bslow= (const float*)d_in[17];
    const float* Wsoma= (const float*)d_in[18];
    const float* bsoma= (const float*)d_in[19];
    const float* Wanc = (const float*)d_in[20];
    const float* banc = (const float*)d_in[21];
    const float* ascl = (const float*)d_in[22];
    const float* blend= (const float*)d_in[23];
    const float* lng  = (const float*)d_in[24];
    const float* lnb  = (const float*)d_in[25];
    float* out = (float*)d_out;

    float* xproj = symaddr(d_xproj);
    float* ctxg  = symaddr(d_ctxg);
    float* bfp   = symaddr(d_bf);
    float* bsp   = symaddr(d_bs);
    float* cfp   = symaddr(d_cf);
    float* csp   = symaddr(d_cs);
    float* gfr   = symaddr(d_gfr);
    float* gsr   = symaddr(d_gsr);
    float* somar = symaddr(d_somar);
    float* qk    = symaddr(d_qk);
    float* pm    = symaddr(d_pm);
    float* cg    = symaddr(d_cg);
    float* xa    = symaddr(d_xa);
    float* ancha = symaddr(d_ancha);
    float* delta = symaddr(d_delta);
    float* carG  = symaddr(d_carG);
    float* carF  = symaddr(d_carF);
    float* carS  = symaddr(d_carS);

    __half* xH    = symaddrh(d_xH);
    __half* ctxgH = symaddrh(d_ctxgH);
    __half* cfH   = symaddrh(d_cfH);
    __half* csH   = symaddrh(d_csH);
    __half* WpH   = symaddrh(d_WpH);
    __half* WxfH  = symaddrh(d_WxfH);
    __half* WxsH  = symaddrh(d_WxsH);
    __half* WcfH  = symaddrh(d_WcfH);
    __half* WcsH  = symaddrh(d_WcsH);
    __half* WfastH= symaddrh(d_WfastH);
    __half* WslowH= symaddrh(d_WslowH);
    __half* WsomaH= symaddrh(d_WsomaH);
    __half* WqkH  = symaddrh(d_WqkH);

    cudaFuncSetAttribute(mma_gemm, cudaFuncAttributeMaxDynamicSharedMemorySize, SMEMSZ);

    dim3 gema(Bb*NCH, Cc/256, 1);
    dim3 gema2(Bb*NCH, Cc/256, 2);

    /* 1: x -> fp16 */
    conv_act<<<(MTOT*192+255)/256, 256>>>(x, xH);

    /* 2: all weight conversions in one launch */
    {
        WConvJobs WJ;
        const float* srcs[10] = {Wp,Wxf,Wxs,Wcf,Wcs,Wfast,Wslow,Wsoma,Wq,Wk};
        __half* dsts[10] = {WpH,WxfH,WxsH,WcfH,WcsH,WfastH,WslowH,WsomaH,
                            WqkH, WqkH + (long)128*KA};
        int ns[10] = {768,768,768,768,768,768,768,768,DKk,DKk};
        int np[10] = {768,768,768,768,768,768,768,768,128,128};
        for (int i=0;i<10;i++){ WJ.src[i]=srcs[i]; WJ.dst[i]=dsts[i]; WJ.nsrc[i]=ns[i]; WJ.npad[i]=np[i]; }
        conv_w_all<<<dim3(576,10), 256>>>(WJ);
    }

    /* 3: ctx_gate EMA on x -> ctxgH */
    {
        EPs E; E.j[0] = {x, ctxg, carG, tau_gate, nullptr, nullptr, ctxgH}; E.j[1] = E.j[0];
        ema_p1<<<gema, 256>>>(E);
        ema_p2<<<dim3((Bb*Cc+255)/256,1,1), 256>>>(E);
        ema_p3s<<<gema, 256>>>(E);
    }

    /* 4: batch1 gemm: xproj (tanh) + qk */
    {
        GemmJobs G = {};
        G.A1[0]=xH;  G.B1[0]=WpH;  G.nseg[0]=1; G.bias[0]=bp;     G.out[0]=xproj; G.Nout[0]=768; G.ncol[0]=6; G.epi[0]=1;
        G.A1[1]=xH;  G.B1[1]=WqkH; G.nseg[1]=1; G.bias[1]=nullptr;G.out[1]=qk;    G.Nout[1]=256; G.ncol[1]=2; G.epi[1]=0;
        mma_gemm<<<dim3(6, MTOT/128, 2), 256, SMEMSZ>>>(G);
    }

    /* 5: content gate cg */
    attn_partmax<<<dim3(Bb*(Tt/TTILE), NSB), 128>>>(qk, pm);
    attn_reduce<<<(MTOT+255)/256, 256>>>(pm, cg);

    /* 6: anchors -> delta (tiny, SIMT) */
    anchor_gather<<<(Bb*Nanc*Cc+255)/256, 256>>>(x, xa);
    gemm_k<<<dim3(Cc/128,1), 256>>>(xa, Wanc, Cc, banc, ancha, Bb*Nanc, Cc, 1);
    delta_k<<<(Bb*Cc+255)/256, 256>>>(ancha, ascl, delta);

    /* 7: batch2 gemm: bf, bs (sigmoid * xproj) */
    {
        GemmJobs G = {};
        G.A1[0]=xH; G.B1[0]=WxfH; G.A2[0]=ctxgH; G.B2[0]=WcfH; G.nseg[0]=2;
        G.bias[0]=bxf; G.mult[0]=xproj; G.out[0]=bfp; G.Nout[0]=768; G.ncol[0]=6; G.epi[0]=2;
        G.A1[1]=xH; G.B1[1]=WxsH; G.A2[1]=ctxgH; G.B2[1]=WcsH; G.nseg[1]=2;
        G.bias[1]=bxs; G.mult[1]=xproj; G.out[1]=bsp; G.Nout[1]=768; G.ncol[1]=6; G.epi[1]=2;
        mma_gemm<<<dim3(6, MTOT/128, 2), 256, SMEMSZ>>>(G);
    }

    /* 8: fast/slow EMAs (z-batched), phase3 fuses *cg + delta, fp16 out */
    {
        EPs E;
        E.j[0] = {bfp, cfp, carF, tau_fast, cg, delta, cfH};
        E.j[1] = {bsp, csp, carS, tau_slow, cg, delta, csH};
        ema_p1<<<gema2, 256>>>(E);
        ema_p2<<<dim3((Bb*Cc+255)/256,1,2), 256>>>(E);
        ema_p3s<<<gema2, 256>>>(E);
    }

    /* 9: batch3 gemm: gfr, gsr, somar */
    {
        GemmJobs G = {};
        G.A1[0]=cfH; G.B1[0]=WfastH; G.nseg[0]=1; G.bias[0]=bfast; G.out[0]=gfr;   G.Nout[0]=768; G.ncol[0]=6; G.epi[0]=0;
        G.A1[1]=csH; G.B1[1]=WslowH; G.nseg[1]=1; G.bias[1]=bslow; G.out[1]=gsr;   G.Nout[1]=768; G.ncol[1]=6; G.epi[1]=0;
        G.A1[2]=xH;  G.B1[2]=WsomaH; G.nseg[2]=1; G.bias[2]=bsoma; G.out[2]=somar; G.Nout[2]=768; G.ncol[2]=6; G.epi[2]=0;
        mma_gemm<<<dim3(6, MTOT/128, 3), 256, SMEMSZ>>>(G);
    }

    /* 10: fused gates + layernorm */
    final_k<<<MTOT, 256>>>(gfr, gsr, somar, blend, lng, lnb, out);
}